// round 15
// baseline (speedup 1.0000x reference)
#include <cuda_runtime.h>
#include <cuda_bf16.h>
#include <cuda_fp16.h>
#include <math.h>
#include <cstdint>

// ---------------- problem constants ----------------
constexpr int Bsz  = 2;
constexpr int Nq   = 2048;
constexpr int My   = 512;
constexpr int Cdim = 1536;
constexpr int Hn   = 12;
constexpr int HDim = 128;          // Cdim / Hn
constexpr int RD   = 64;
constexpr int Sk   = Nq + My;      // 2560
constexpr float EPSV  = 1e-6f;
constexpr float SCALE = 0.08838834764831845f;   // 1/sqrt(128)

// ---------------- scratch (static device arrays; no allocs allowed) ----------------
__device__ float g_qkv [(long long)Bsz * Nq * 3 * Cdim];
__device__ float g_kvr [(long long)Bsz * My * 2 * Cdim];
__device__ float g_Vb  [(long long)Bsz * Hn * Sk * HDim];   // V fp32 [bh][s][d]

// fp16 operands for weight GEMMs (activations single, weights split hi/lo)
__device__ __half g_xh [(long long)Bsz * Nq * Cdim];
__device__ __half g_yh [(long long)Bsz * My * Cdim];
__device__ __half g_Wqkvh[(long long)3 * Cdim * Cdim];
__device__ __half g_Wqkvl[(long long)3 * Cdim * Cdim];
__device__ __half g_Wkvh [(long long)2 * Cdim * Cdim];
__device__ __half g_Wkvl [(long long)2 * Cdim * Cdim];
__device__ __half g_Wph  [(long long)Cdim * Cdim];
__device__ __half g_Wpl  [(long long)Cdim * Cdim];
__device__ __half g_Oh   [(long long)Bsz * Nq * Cdim];      // attention output (single fp16)
// attention split operands (bf16, 3-product path — unchanged)
__device__ __nv_bfloat16 g_Qh [(long long)Bsz * Hn * Nq * HDim];
__device__ __nv_bfloat16 g_Ql [(long long)Bsz * Hn * Nq * HDim];
__device__ __nv_bfloat16 g_Kh [(long long)Bsz * Hn * Sk * HDim];
__device__ __nv_bfloat16 g_Kl [(long long)Bsz * Hn * Sk * HDim];
__device__ __nv_bfloat16 g_Vth[(long long)Bsz * Hn * HDim * Sk];  // V^T [bh][d][s]
__device__ __nv_bfloat16 g_Vtl[(long long)Bsz * Hn * HDim * Sk];

// ---------------- small PTX helpers (baseline PTX only) ----------------
__device__ __forceinline__ uint32_t smem_u32(const void* p) {
    uint32_t a;
    asm("{ .reg .u64 t; cvta.to.shared.u64 t, %1; cvt.u32.u64 %0, t; }" : "=r"(a) : "l"(p));
    return a;
}
__device__ __forceinline__ void cp16(uint32_t dst, const void* src) {
    asm volatile("cp.async.cg.shared.global [%0], [%1], 16;" :: "r"(dst), "l"(src));
}
#define CP_COMMIT()  asm volatile("cp.async.commit_group;" ::: "memory")
#define CP_WAIT(n)   asm volatile("cp.async.wait_group %0;" :: "n"(n) : "memory")

__device__ __forceinline__ void mma_bf16(float d[4], const uint32_t a[4], const uint32_t b[2]) {
    asm volatile(
        "mma.sync.aligned.m16n8k16.row.col.f32.bf16.bf16.f32 "
        "{%0,%1,%2,%3}, {%4,%5,%6,%7}, {%8,%9}, {%0,%1,%2,%3};"
        : "+f"(d[0]), "+f"(d[1]), "+f"(d[2]), "+f"(d[3])
        : "r"(a[0]), "r"(a[1]), "r"(a[2]), "r"(a[3]), "r"(b[0]), "r"(b[1]));
}
__device__ __forceinline__ void mma_fp16(float d[4], const uint32_t a[4], const uint32_t b[2]) {
    asm volatile(
        "mma.sync.aligned.m16n8k16.row.col.f32.f16.f16.f32 "
        "{%0,%1,%2,%3}, {%4,%5,%6,%7}, {%8,%9}, {%0,%1,%2,%3};"
        : "+f"(d[0]), "+f"(d[1]), "+f"(d[2]), "+f"(d[3])
        : "r"(a[0]), "r"(a[1]), "r"(a[2]), "r"(a[3]), "r"(b[0]), "r"(b[1]));
}
__device__ __forceinline__ void split_write(float v, __nv_bfloat16* h, __nv_bfloat16* l, long long idx) {
    const __nv_bfloat16 hb = __float2bfloat16(v);
    h[idx] = hb;
    l[idx] = __float2bfloat16(v - __bfloat162float(hb));
}
__device__ __forceinline__ uint32_t pack_bf2(float a, float b) {
    __nv_bfloat162 v; v.x = __float2bfloat16(a); v.y = __float2bfloat16(b);
    return *(uint32_t*)&v;
}

// ---------------- 128x128 fp16 2-product HMMA GEMM core (triple-buffered) ----------
// C[M,N] = A[M,K] @ W[K,N], A single fp16 [M,K]; W split fp16 (Wh+Wl) [N,K] transposed.
// One __syncthreads per K-chunk: barrier at iter c proves compute(c-1) done by all
// threads; the buffer staged at iter c is (c+2)%3 == (c-1)%3, so reuse is race-free.
constexpr int MM_STRIDE_B = 80;
constexpr int MM_ARR_B    = 128 * MM_STRIDE_B;   // 10240
constexpr int MM_BUF_B    = 3 * MM_ARR_B;        // A, Bh, Bl = 30720
constexpr int MM_SMEM_B   = 3 * MM_BUF_B;        // 92160 (3 stage buffers)

constexpr int QKV_COLT = 3 * Cdim / 128;     // 36
constexpr int QKV_CTAS = QKV_COLT * (Bsz * Nq / 128);   // 1152
constexpr int KV_COLT  = 2 * Cdim / 128;     // 24
constexpr int FUSED_CTAS = QKV_CTAS + KV_COLT * (Bsz * My / 128);  // 1344

#define MM_BODY(AP, BhP, BlP)                                                               \
    const int s0   = tid * 2;                                                               \
    const int row_s0 = s0 >> 2,  q_s0 = s0 & 3;                                             \
    const int row_s1 = (s0 + 1) >> 2, q_s1 = (s0 + 1) & 3;                                  \
    auto stage = [&](int c, int buf) {                                                      \
        const long long k0 = (long long)c * 32;                                             \
        const uint32_t db = sbase + buf * MM_BUF_B;                                         \
        {                                                                                   \
            const long long ga = (long long)(row0 + row_s0) * Cdim + k0 + q_s0 * 8;         \
            const long long gb = (long long)(col0 + row_s0) * Cdim + k0 + q_s0 * 8;         \
            const uint32_t  so = row_s0 * MM_STRIDE_B + q_s0 * 16;                          \
            cp16(db + 0 * MM_ARR_B + so, (AP) + ga);                                        \
            cp16(db + 1 * MM_ARR_B + so, (BhP) + gb);                                       \
            cp16(db + 2 * MM_ARR_B + so, (BlP) + gb);                                       \
        }                                                                                   \
        {                                                                                   \
            const long long ga = (long long)(row0 + row_s1) * Cdim + k0 + q_s1 * 8;         \
            const long long gb = (long long)(col0 + row_s1) * Cdim + k0 + q_s1 * 8;         \
            const uint32_t  so = row_s1 * MM_STRIDE_B + q_s1 * 16;                          \
            cp16(db + 0 * MM_ARR_B + so, (AP) + ga);                                        \
            cp16(db + 1 * MM_ARR_B + so, (BhP) + gb);                                       \
            cp16(db + 2 * MM_ARR_B + so, (BlP) + gb);                                       \
        }                                                                                   \
    };                                                                                      \
    float acc[4][4][4];                                                                     \
    _Pragma("unroll")                                                                       \
    for (int i = 0; i < 4; i++)                                                             \
        _Pragma("unroll")                                                                   \
        for (int j = 0; j < 4; j++)                                                         \
            _Pragma("unroll")                                                               \
            for (int r = 0; r < 4; r++) acc[i][j][r] = 0.f;                                 \
    constexpr int nch = Cdim / 32;                                                          \
    stage(0, 0); CP_COMMIT();                                                               \
    stage(1, 1); CP_COMMIT();                                                               \
    for (int c = 0; c < nch; c++) {                                                         \
        if (c + 1 < nch) { CP_WAIT(1); } else { CP_WAIT(0); }                               \
        __syncthreads();                                                                    \
        if (c + 2 < nch) { stage(c + 2, (c + 2) % 3); CP_COMMIT(); }                        \
        const char* bp = smem + (c % 3) * MM_BUF_B;                                         \
        const char* pA  = bp;                                                               \
        const char* pBh = bp + 1 * MM_ARR_B;                                                \
        const char* pBl = bp + 2 * MM_ARR_B;                                                \
        _Pragma("unroll")                                                                   \
        for (int kk = 0; kk < 2; kk++) {                                                    \
            const int cbyte = (kk * 16 + 2 * tg) * 2;                                       \
            uint32_t av[4][4], bh[4][2], bl[4][2];                                          \
            _Pragma("unroll")                                                               \
            for (int mt = 0; mt < 4; mt++) {                                                \
                const int r = wm + mt * 16 + g;                                             \
                av[mt][0] = *(const uint32_t*)(pA + r * MM_STRIDE_B + cbyte);               \
                av[mt][1] = *(const uint32_t*)(pA + (r + 8) * MM_STRIDE_B + cbyte);         \
                av[mt][2] = *(const uint32_t*)(pA + r * MM_STRIDE_B + cbyte + 16);          \
                av[mt][3] = *(const uint32_t*)(pA + (r + 8) * MM_STRIDE_B + cbyte + 16);    \
            }                                                                               \
            _Pragma("unroll")                                                               \
            for (int nt = 0; nt < 4; nt++) {                                                \
                const int n = wn + nt * 8 + g;                                              \
                bh[nt][0] = *(const uint32_t*)(pBh + n * MM_STRIDE_B + cbyte);              \
                bh[nt][1] = *(const uint32_t*)(pBh + n * MM_STRIDE_B + cbyte + 16);         \
                bl[nt][0] = *(const uint32_t*)(pBl + n * MM_STRIDE_B + cbyte);              \
                bl[nt][1] = *(const uint32_t*)(pBl + n * MM_STRIDE_B + cbyte + 16);         \
            }                                                                               \
            _Pragma("unroll")                                                               \
            for (int mt = 0; mt < 4; mt++)                                                  \
                _Pragma("unroll")                                                           \
                for (int nt = 0; nt < 4; nt++) {                                            \
                    mma_fp16(acc[mt][nt], av[mt], bh[nt]);                                  \
                    mma_fp16(acc[mt][nt], av[mt], bl[nt]);                                  \
                }                                                                           \
        }                                                                                   \
    }

// ---- fused QKV + KV weight GEMM ----
__global__ __launch_bounds__(256, 2)
void mma_gemm_fused(const __half* __restrict__ xh,
                    const __half* __restrict__ Wqh, const __half* __restrict__ Wql,
                    float* __restrict__ Cq,
                    const __half* __restrict__ yh,
                    const __half* __restrict__ Wkh, const __half* __restrict__ Wkl,
                    float* __restrict__ Ck)
{
    extern __shared__ char smem[];
    const uint32_t sbase = smem_u32(smem);

    const int tid  = threadIdx.x;
    const int lane = tid & 31;
    const int wid  = tid >> 5;
    const int wm   = (wid >> 2) * 64;
    const int wn   = (wid & 3) * 32;
    const int g    = lane >> 2;
    const int tg   = lane & 3;

    const int bid = blockIdx.x;
    const __half *A, *Bh, *Bl;
    float* C;
    int row0, col0, ldc;
    if (bid < QKV_CTAS) {
        A = xh; Bh = Wqh; Bl = Wql; C = Cq;
        row0 = (bid / QKV_COLT) * 128;
        col0 = (bid % QKV_COLT) * 128;
        ldc  = 3 * Cdim;
    } else {
        const int b2 = bid - QKV_CTAS;
        A = yh; Bh = Wkh; Bl = Wkl; C = Ck;
        row0 = (b2 / KV_COLT) * 128;
        col0 = (b2 % KV_COLT) * 128;
        ldc  = 2 * Cdim;
    }

    MM_BODY(A, Bh, Bl)

    #pragma unroll
    for (int nt = 0; nt < 4; nt++) {
        const int col = col0 + wn + nt * 8 + 2 * tg;
        #pragma unroll
        for (int mt = 0; mt < 4; mt++) {
            const int r = row0 + wm + mt * 16 + g;
            float2 v0, v1;
            v0.x = acc[mt][nt][0]; v0.y = acc[mt][nt][1];
            v1.x = acc[mt][nt][2]; v1.y = acc[mt][nt][3];
            *(float2*)(C + (long long)r * ldc + col)       = v0;
            *(float2*)(C + (long long)(r + 8) * ldc + col) = v1;
        }
    }
}

// ---- proj GEMM (bias): A = attention O (single fp16), B = Wproj split ----
__global__ __launch_bounds__(256, 2)
void mma_gemm_proj(const __half* __restrict__ Ap,
                   const __half* __restrict__ Bhp, const __half* __restrict__ Blp,
                   float* __restrict__ C, const float* __restrict__ bias)
{
    extern __shared__ char smem[];
    const uint32_t sbase = smem_u32(smem);

    const int tid  = threadIdx.x;
    const int lane = tid & 31;
    const int wid  = tid >> 5;
    const int row0 = blockIdx.y * 128;
    const int col0 = blockIdx.x * 128;
    const int wm   = (wid >> 2) * 64;
    const int wn   = (wid & 3) * 32;
    const int g    = lane >> 2;
    const int tg   = lane & 3;

    MM_BODY(Ap, Bhp, Blp)

    #pragma unroll
    for (int nt = 0; nt < 4; nt++) {
        const int col = col0 + wn + nt * 8 + 2 * tg;
        const float b0 = bias[col], b1 = bias[col + 1];
        #pragma unroll
        for (int mt = 0; mt < 4; mt++) {
            const int r = row0 + wm + mt * 16 + g;
            float2 v0, v1;
            v0.x = acc[mt][nt][0] + b0; v0.y = acc[mt][nt][1] + b1;
            v1.x = acc[mt][nt][2] + b0; v1.y = acc[mt][nt][3] + b1;
            *(float2*)(C + (long long)r * Cdim + col)       = v0;
            *(float2*)(C + (long long)(r + 8) * Cdim + col) = v1;
        }
    }
}

// ---------------- fused attention v3 (R13/R14-proven) ----------------
constexpr int FA_NIT  = Sk / 64;                 // 40
constexpr int F3_QH   = 0;
constexpr int F3_QL   = 34816;
constexpr int F3_K0   = 69632;
constexpr int F3_KBUF = 34816;
constexpr int F3_KLOF = 17408;
constexpr int F3_VH   = 139264;
constexpr int F3_VL   = 157696;
constexpr int F3_YB   = 176128;
constexpr int FA_SMEM = 178176;

__global__ __launch_bounds__(256, 1)
void fused_attn(const __nv_bfloat16* __restrict__ Qh, const __nv_bfloat16* __restrict__ Ql,
                const __nv_bfloat16* __restrict__ Kh, const __nv_bfloat16* __restrict__ Kl,
                const __nv_bfloat16* __restrict__ Vth, const __nv_bfloat16* __restrict__ Vtl,
                const float* __restrict__ ytw,
                __half* __restrict__ Oh)
{
    extern __shared__ char smem[];
    const uint32_t sb = smem_u32(smem);

    const int z  = blockIdx.y;
    const int q0 = blockIdx.x * 128;
    const int b  = z / Hn;
    const int h  = z % Hn;

    const int tid  = threadIdx.x;
    const int lane = tid & 31;
    const int wid  = tid >> 5;
    const int g    = lane >> 2;
    const int tg   = lane & 3;
    const int wm   = wid * 16;

    const __nv_bfloat16* Qhp = Qh + (long long)z * Nq * HDim;
    const __nv_bfloat16* Qlp = Ql + (long long)z * Nq * HDim;
    const __nv_bfloat16* Khp = Kh + (long long)z * Sk * HDim;
    const __nv_bfloat16* Klp = Kl + (long long)z * Sk * HDim;
    const __nv_bfloat16* Vhp = Vth + (long long)z * HDim * Sk;
    const __nv_bfloat16* Vlp = Vtl + (long long)z * HDim * Sk;

    float* sYB = (float*)(smem + F3_YB);
    #pragma unroll
    for (int j = 0; j < 2; j++) {
        const int i = tid + j * 256;
        sYB[i] = logf(fmaxf(ytw[b * My + i], 1e-4f));
    }

    #pragma unroll
    for (int j = 0; j < 8; j++) {
        const int id = tid + j * 256, r = id >> 4, c = id & 15;
        cp16(sb + F3_QH + r * 272 + c * 16, Qhp + (long long)(q0 + r) * HDim + c * 8);
        cp16(sb + F3_QL + r * 272 + c * 16, Qlp + (long long)(q0 + r) * HDim + c * 8);
    }
    CP_COMMIT();
    #pragma unroll
    for (int j = 0; j < 4; j++) {
        const int id = tid + j * 256, r = id >> 4, c = id & 15;
        cp16(sb + F3_K0 +           r * 272 + c * 16, Khp + (long long)r * HDim + c * 8);
        cp16(sb + F3_K0 + F3_KLOF + r * 272 + c * 16, Klp + (long long)r * HDim + c * 8);
    }
    CP_COMMIT();

    float oacc[16][4];
    #pragma unroll
    for (int i = 0; i < 16; i++)
        #pragma unroll
        for (int r = 0; r < 4; r++) oacc[i][r] = 0.f;
    float rowsum0 = 0.f, rowsum1 = 0.f;

    for (int it = 0; it < FA_NIT; it++) {
        __syncthreads();

        if (it + 1 < FA_NIT) {
            const uint32_t kb = sb + F3_K0 + ((it + 1) & 1) * F3_KBUF;
            const int sblk = (it + 1) * 64;
            #pragma unroll
            for (int j = 0; j < 4; j++) {
                const int id = tid + j * 256, r = id >> 4, c = id & 15;
                cp16(kb +           r * 272 + c * 16, Khp + (long long)(sblk + r) * HDim + c * 8);
                cp16(kb + F3_KLOF + r * 272 + c * 16, Klp + (long long)(sblk + r) * HDim + c * 8);
            }
        }
        CP_COMMIT();
        #pragma unroll
        for (int j = 0; j < 4; j++) {
            const int id = tid + j * 256, d = id >> 3, c = id & 7;
            cp16(sb + F3_VH + d * 144 + c * 16, Vhp + (long long)d * Sk + it * 64 + c * 8);
            cp16(sb + F3_VL + d * 144 + c * 16, Vlp + (long long)d * Sk + it * 64 + c * 8);
        }
        CP_COMMIT();

        CP_WAIT(2);
        __syncthreads();

        const uint32_t kcur = sb + F3_K0 + (it & 1) * F3_KBUF;
        float sacc[8][4];
        #pragma unroll
        for (int i = 0; i < 8; i++)
            #pragma unroll
            for (int r = 0; r < 4; r++) sacc[i][r] = 0.f;

        #pragma unroll
        for (int kk = 0; kk < 8; kk++) {
            const int cb = kk * 32 + tg * 4;
            uint32_t qh_[4], ql_[4], kh_[8][2], kl_[8][2];
            {
                const char* p = smem + F3_QH + (wm + g) * 272 + cb;
                qh_[0] = *(const uint32_t*)(p);
                qh_[1] = *(const uint32_t*)(p + 8 * 272);
                qh_[2] = *(const uint32_t*)(p + 16);
                qh_[3] = *(const uint32_t*)(p + 8 * 272 + 16);
                const char* q = p + (F3_QL - F3_QH);
                ql_[0] = *(const uint32_t*)(q);
                ql_[1] = *(const uint32_t*)(q + 8 * 272);
                ql_[2] = *(const uint32_t*)(q + 16);
                ql_[3] = *(const uint32_t*)(q + 8 * 272 + 16);
            }
            #pragma unroll
            for (int nt = 0; nt < 8; nt++) {
                const char* p = (const char*)smem + (kcur - sb) + (nt * 8 + g) * 272 + cb;
                kh_[nt][0] = *(const uint32_t*)(p);
                kh_[nt][1] = *(const uint32_t*)(p + 16);
                kl_[nt][0] = *(const uint32_t*)(p + F3_KLOF);
                kl_[nt][1] = *(const uint32_t*)(p + F3_KLOF + 16);
            }
            #pragma unroll
            for (int nt = 0; nt < 8; nt++) {
                mma_bf16(sacc[nt], qh_, kh_[nt]);
                mma_bf16(sacc[nt], qh_, kl_[nt]);
                mma_bf16(sacc[nt], ql_, kh_[nt]);
            }
        }

        uint32_t ph_[4][4], pl_[4][4];
        #pragma unroll
        for (int nt = 0; nt < 8; nt++) {
            const int col0 = nt * 8 + 2 * tg;
            const int gc   = it * 64 + col0;
            float b0 = 0.f, b1 = 0.f;
            if (gc >= Nq) { b0 = sYB[gc - Nq]; b1 = sYB[gc - Nq + 1]; }
            const float p0 = __expf(sacc[nt][0] * SCALE + b0);
            const float p1 = __expf(sacc[nt][1] * SCALE + b1);
            const float p2 = __expf(sacc[nt][2] * SCALE + b0);
            const float p3 = __expf(sacc[nt][3] * SCALE + b1);
            rowsum0 += p0 + p1;
            rowsum1 += p2 + p3;
            const int j  = nt >> 1;
            const int rb = (nt & 1) * 2;
            const uint32_t h01 = pack_bf2(p0, p1);
            const uint32_t h23 = pack_bf2(p2, p3);
            ph_[j][rb + 0] = h01;
            ph_[j][rb + 1] = h23;
            const __nv_bfloat162 hb01 = *(const __nv_bfloat162*)&h01;
            const __nv_bfloat162 hb23 = *(const __nv_bfloat162*)&h23;
            pl_[j][rb + 0] = pack_bf2(p0 - __bfloat162float(hb01.x), p1 - __bfloat162float(hb01.y));
            pl_[j][rb + 1] = pack_bf2(p2 - __bfloat162float(hb23.x), p3 - __bfloat162float(hb23.y));
        }

        CP_WAIT(1);
        __syncthreads();

        #pragma unroll
        for (int j = 0; j < 4; j++) {
            const int cb = j * 32 + tg * 4;
            #pragma unroll
            for (int nt = 0; nt < 16; nt++) {
                uint32_t vh_[2], vl_[2];
                const char* p = smem + F3_VH + (nt * 8 + g) * 144 + cb;
                vh_[0] = *(const uint32_t*)(p);
                vh_[1] = *(const uint32_t*)(p + 16);
                vl_[0] = *(const uint32_t*)(p + (F3_VL - F3_VH));
                vl_[1] = *(const uint32_t*)(p + (F3_VL - F3_VH) + 16);
                mma_bf16(oacc[nt], ph_[j], vh_);
                mma_bf16(oacc[nt], ph_[j], vl_);
                mma_bf16(oacc[nt], pl_[j], vh_);
            }
        }
    }

    rowsum0 += __shfl_xor_sync(0xffffffffu, rowsum0, 1);
    rowsum0 += __shfl_xor_sync(0xffffffffu, rowsum0, 2);
    rowsum1 += __shfl_xor_sync(0xffffffffu, rowsum1, 1);
    rowsum1 += __shfl_xor_sync(0xffffffffu, rowsum1, 2);
    const float inv0 = 1.f / rowsum0;
    const float inv1 = 1.f / rowsum1;

    const int r = wm + g;
    #pragma unroll
    for (int nt = 0; nt < 16; nt++) {
        const int col = nt * 8 + 2 * tg;
        const long long o0 = ((long long)b * Nq + q0 + r) * Cdim + h * HDim + col;
        const long long o1 = o0 + 8LL * Cdim;
        __half2 v0, v1;
        v0.x = __float2half(oacc[nt][0] * inv0);
        v0.y = __float2half(oacc[nt][1] * inv0);
        v1.x = __float2half(oacc[nt][2] * inv1);
        v1.y = __float2half(oacc[nt][3] * inv1);
        *(__half2*)(Oh + o0) = v0;
        *(__half2*)(Oh + o1) = v1;
    }
}

// ---------------- fp32 -> single fp16, two tensors in one launch ----------------
__global__ void cvt_single2(const float* __restrict__ s1, __half* __restrict__ h1, long long n1,
                            const float* __restrict__ s2, __half* __restrict__ h2, long long n2)
{
    long long i = ((long long)blockIdx.x * blockDim.x + threadIdx.x) * 4;
    const float* src; __half* h;
    if (i < n1) { src = s1; h = h1; }
    else        { i -= n1; if (i >= n2) return; src = s2; h = h2; }
    const float4 v = *(const float4*)(src + i);
    __half hb[4];
    hb[0] = __float2half(v.x); hb[1] = __float2half(v.y);
    hb[2] = __float2half(v.z); hb[3] = __float2half(v.w);
    *(uint2*)(h + i) = *(uint2*)hb;
}

// ---------------- fp32 [K][N] -> split fp16 transposed [N][K]; 2 weights packed ----
constexpr int WQ_BLKS = (3 * Cdim / 32) * (Cdim / 32);   // 6912
constexpr int WK_BLKS = (2 * Cdim / 32) * (Cdim / 32);   // 4608

__global__ void cvt_split_T2(const float* __restrict__ W1, __half* __restrict__ h1,
                             __half* __restrict__ l1,
                             const float* __restrict__ W2, __half* __restrict__ h2,
                             __half* __restrict__ l2)
{
    __shared__ float tile[32][33];
    const int tid = threadIdx.x;
    const int tx = tid & 31;
    const int ty = tid >> 5;

    const float* W; __half *h, *l;
    int N, n0, k0;
    int bid = blockIdx.x;
    if (bid < WQ_BLKS) {
        W = W1; h = h1; l = l1; N = 3 * Cdim;
        n0 = (bid % (N / 32)) * 32;  k0 = (bid / (N / 32)) * 32;
    } else {
        bid -= WQ_BLKS;
        W = W2; h = h2; l = l2; N = 2 * Cdim;
        n0 = (bid % (N / 32)) * 32;  k0 = (bid / (N / 32)) * 32;
    }

    #pragma unroll
    for (int i = ty; i < 32; i += 8)
        tile[i][tx] = W[(long long)(k0 + i) * N + n0 + tx];
    __syncthreads();
    #pragma unroll
    for (int i = ty; i < 32; i += 8) {
        const float v = tile[tx][i];
        const __half hb = __float2half(v);
        const __half lb = __float2half(v - __half2float(hb));
        const long long o = (long long)(n0 + i) * Cdim + k0 + tx;
        h[o] = hb; l[o] = lb;
    }
}

// ---------------- single-weight transposed split fp16 (Wproj) ----------------
__global__ void cvt_split_T(const float* __restrict__ W, __half* __restrict__ h,
                            __half* __restrict__ l, int K, int N)
{
    __shared__ float tile[32][33];
    const int k0 = blockIdx.y * 32;
    const int n0 = blockIdx.x * 32;
    const int tx = threadIdx.x;
    const int ty = threadIdx.y;
    #pragma unroll
    for (int i = ty; i < 32; i += 8)
        tile[i][tx] = W[(long long)(k0 + i) * N + n0 + tx];
    __syncthreads();
    #pragma unroll
    for (int i = ty; i < 32; i += 8) {
        const float v = tile[tx][i];
        const __half hb = __float2half(v);
        const __half lb = __float2half(v - __half2float(hb));
        const long long o = (long long)(n0 + i) * K + k0 + tx;
        h[o] = hb; l[o] = lb;
    }
}

// ---------------- V: fp32 [bh][s][d] -> split bf16 transposed [bh][d][s] ----------
__global__ void v_transpose_split(const float* __restrict__ Vb,
                                  __nv_bfloat16* __restrict__ Vth,
                                  __nv_bfloat16* __restrict__ Vtl)
{
    __shared__ float tile[32][33];
    const int z  = blockIdx.z;
    const int ss0 = blockIdx.x * 32;
    const int dd0 = blockIdx.y * 32;
    const int tx = threadIdx.x;
    const int ty = threadIdx.y;
    const long long ib = (long long)z * Sk * HDim;
    const long long ob = (long long)z * HDim * Sk;
    #pragma unroll
    for (int i = ty; i < 32; i += 8)
        tile[i][tx] = Vb[ib + (long long)(ss0 + i) * HDim + dd0 + tx];
    __syncthreads();
    #pragma unroll
    for (int i = ty; i < 32; i += 8) {
        const float v = tile[tx][i];
        const __nv_bfloat16 hb = __float2bfloat16(v);
        const __nv_bfloat16 lb = __float2bfloat16(v - __bfloat162float(hb));
        const long long o = ob + (long long)(dd0 + i) * Sk + ss0 + tx;
        Vth[o] = hb; Vtl[o] = lb;
    }
}

// ---------------- warp reduction helpers ----------------
__device__ __forceinline__ float warpSum(float v) {
    #pragma unroll
    for (int o = 16; o > 0; o >>= 1) v += __shfl_xor_sync(0xffffffffu, v, o);
    return v;
}

// ---------------- QKV postprocess: RMSNorm + RoPE -> split bf16 Q,K; fp32 V ------
__global__ void qkv_post(const float* __restrict__ qkv, const float* __restrict__ pos,
                         const float* __restrict__ qw, const float* __restrict__ kw,
                         __nv_bfloat16* __restrict__ Qh, __nv_bfloat16* __restrict__ Ql,
                         __nv_bfloat16* __restrict__ Kh, __nv_bfloat16* __restrict__ Kl,
                         float* __restrict__ Vb)
{
    const int idx = blockIdx.x;
    const int h  = idx % Hn;
    const int bn = idx / Hn;
    const int n  = bn % Nq;
    const int b  = bn / Nq;
    const int d  = threadIdx.x;

    const float* row = qkv + (long long)bn * (3 * Cdim);
    const float qv = row[h * HDim + d];
    const float kv = row[Cdim + h * HDim + d];
    const float vv = row[2 * Cdim + h * HDim + d];

    __shared__ float sred[8];
    __shared__ float qs[HDim], ks[HDim];

    const float sq = warpSum(qv * qv);
    const float sk = warpSum(kv * kv);
    const int lane = d & 31, w = d >> 5;
    if (lane == 0) { sred[w] = sq; sred[4 + w] = sk; }
    __syncthreads();
    const float sumq = sred[0] + sred[1] + sred[2] + sred[3];
    const float sumk = sred[4] + sred[5] + sred[6] + sred[7];
    const float rq = rsqrtf(sumq * (1.0f / HDim) + EPSV);
    const float rk = rsqrtf(sumk * (1.0f / HDim) + EPSV);
    const float qn = qw[d] * qv * rq;
    const float kn = kw[d] * kv * rk;
    qs[d] = qn; ks[d] = kn;
    __syncthreads();

    float qo = qn, ko = kn;
    if (d < RD) {
        const int j = d & 31;
        const float c = pos[(n * 32 + j) * 2 + 0];
        const float s = pos[(n * 32 + j) * 2 + 1];
        if (d < RD / 2) { qo = qs[d] * c - qs[d + 32] * s;  ko = ks[d] * c - ks[d + 32] * s; }
        else            { qo = qs[d - 32] * s + qs[d] * c;  ko = ks[d - 32] * s + ks[d] * c; }
    }
    const long long qi = (((long long)(b * Hn + h)) * Nq + n) * HDim + d;
    const long long ki = (((long long)(b * Hn + h)) * Sk + n) * HDim + d;
    split_write(qo, Qh, Ql, qi);
    split_write(ko, Kh, Kl, ki);
    Vb[ki] = vv;
}

// ---------------- KV(y) postprocess ----------------
__global__ void kv_post(const float* __restrict__ kvr, const float* __restrict__ kw,
                        __nv_bfloat16* __restrict__ Kh, __nv_bfloat16* __restrict__ Kl,
                        float* __restrict__ Vb)
{
    const int idx = blockIdx.x;
    const int h  = idx % Hn;
    const int bm = idx / Hn;
    const int m  = bm % My;
    const int b  = bm / My;
    const int d  = threadIdx.x;

    const float* row = kvr + (long long)bm * (2 * Cdim);
    const float kv = row[h * HDim + d];
    const float vv = row[Cdim + h * HDim + d];

    __shared__ float sred[4];
    const float sk = warpSum(kv * kv);
    if ((d & 31) == 0) sred[d >> 5] = sk;
    __syncthreads();
    const float sumk = sred[0] + sred[1] + sred[2] + sred[3];
    const float rk = rsqrtf(sumk * (1.0f / HDim) + EPSV);
    const float kn = kw[d] * kv * rk;

    const long long ki = (((long long)(b * Hn + h)) * Sk + (Nq + m)) * HDim + d;
    split_write(kn, Kh, Kl, ki);
    Vb[ki] = vv;
}

// ---------------- launch ----------------
extern "C" void kernel_launch(void* const* d_in, const int* in_sizes, int n_in,
                              void* d_out, int out_size)
{
    const float* x    = (const float*)d_in[0];
    const float* y    = (const float*)d_in[1];
    const float* pos  = (const float*)d_in[2];
    const float* ytw  = (const float*)d_in[3];
    const float* Wqkv = (const float*)d_in[4];
    const float* Wkv  = (const float*)d_in[5];
    const float* qw   = (const float*)d_in[6];
    const float* kw   = (const float*)d_in[7];
    const float* Wproj= (const float*)d_in[8];
    const float* bproj= (const float*)d_in[9];
    float* out = (float*)d_out;

    float *qkv, *kvr, *Vb;
    cudaGetSymbolAddress((void**)&qkv, g_qkv);
    cudaGetSymbolAddress((void**)&kvr, g_kvr);
    cudaGetSymbolAddress((void**)&Vb,  g_Vb);

    __half *xh,*yh,*Wqh,*Wql,*Wkh,*Wkl,*Wph,*Wpl,*Oh;
    __nv_bfloat16 *Qh,*Ql,*Kh,*Kl,*Vth,*Vtl;
    cudaGetSymbolAddress((void**)&xh, g_xh);
    cudaGetSymbolAddress((void**)&yh, g_yh);
    cudaGetSymbolAddress((void**)&Wqh, g_Wqkvh); cudaGetSymbolAddress((void**)&Wql, g_Wqkvl);
    cudaGetSymbolAddress((void**)&Wkh, g_Wkvh);  cudaGetSymbolAddress((void**)&Wkl, g_Wkvl);
    cudaGetSymbolAddress((void**)&Wph, g_Wph);   cudaGetSymbolAddress((void**)&Wpl, g_Wpl);
    cudaGetSymbolAddress((void**)&Oh, g_Oh);
    cudaGetSymbolAddress((void**)&Qh, g_Qh);     cudaGetSymbolAddress((void**)&Ql, g_Ql);
    cudaGetSymbolAddress((void**)&Kh, g_Kh);     cudaGetSymbolAddress((void**)&Kl, g_Kl);
    cudaGetSymbolAddress((void**)&Vth, g_Vth);   cudaGetSymbolAddress((void**)&Vtl, g_Vtl);

    cudaFuncSetAttribute(mma_gemm_fused, cudaFuncAttributeMaxDynamicSharedMemorySize, MM_SMEM_B);
    cudaFuncSetAttribute(mma_gemm_proj,  cudaFuncAttributeMaxDynamicSharedMemorySize, MM_SMEM_B);
    cudaFuncSetAttribute(fused_attn, cudaFuncAttributeMaxDynamicSharedMemorySize, FA_SMEM);

    // 0) conversions
    const long long nx = (long long)Bsz * Nq * Cdim;
    const long long ny = (long long)Bsz * My * Cdim;
    cvt_single2<<<(int)(((nx + ny) / 4 + 255) / 256), 256>>>(x, xh, nx, y, yh, ny);
    cvt_split_T2<<<WQ_BLKS + WK_BLKS, 256>>>(Wqkv, Wqh, Wql, Wkv, Wkh, Wkl);
    cvt_split_T<<<dim3(Cdim / 32, Cdim / 32), dim3(32, 8)>>>(Wproj, Wph, Wpl, Cdim, Cdim);

    // 1+2) fused QKV + KV weight GEMM (fp16 2-product, triple-buffered)
    mma_gemm_fused<<<FUSED_CTAS, 256, MM_SMEM_B>>>(
        xh, Wqh, Wql, qkv, yh, Wkh, Wkl, kvr);

    // 3) postprocess
    qkv_post<<<Bsz * Nq * Hn, HDim>>>(qkv, pos, qw, kw, Qh, Ql, Kh, Kl, Vb);
    kv_post<<<Bsz * My * Hn, HDim>>>(kvr, kw, Kh, Kl, Vb);
    v_transpose_split<<<dim3(Sk / 32, HDim / 32, Bsz * Hn), dim3(32, 8)>>>(Vb, Vth, Vtl);

    // 4-6) fused attention v3 -> single fp16 O
    fused_attn<<<dim3(Nq / 128, Bsz * Hn), 256, FA_SMEM>>>(
        Qh, Ql, Kh, Kl, Vth, Vtl, ytw, Oh);

    // 7) out = O @ Wproj + bproj (fp16 2-product, triple-buffered)
    mma_gemm_proj<<<dim3(Cdim / 128, Bsz * Nq / 128), 256, MM_SMEM_B>>>(
        Oh, Wph, Wpl, out, bproj);
}

// round 16
// speedup vs baseline: 1.1076x; 1.1076x over previous
#include <cuda_runtime.h>
#include <cuda_bf16.h>
#include <cuda_fp16.h>
#include <math.h>
#include <cstdint>

// ---------------- problem constants ----------------
constexpr int Bsz  = 2;
constexpr int Nq   = 2048;
constexpr int My   = 512;
constexpr int Cdim = 1536;
constexpr int Hn   = 12;
constexpr int HDim = 128;          // Cdim / Hn
constexpr int RD   = 64;
constexpr int Sk   = Nq + My;      // 2560
constexpr float EPSV  = 1e-6f;
constexpr float SCALE = 0.08838834764831845f;   // 1/sqrt(128)
constexpr float SHIFT = 5.545177444479562f;     // 8*ln2; cancels in softmax, keeps P in fp16 range

// ---------------- scratch (static device arrays; no allocs allowed) ----------------
__device__ float g_qkv [(long long)Bsz * Nq * 3 * Cdim];
__device__ float g_kvr [(long long)Bsz * My * 2 * Cdim];
__device__ float g_Vb  [(long long)Bsz * Hn * Sk * HDim];   // V fp32 [bh][s][d]

// fp16 operands for weight GEMMs (activations single, weights split hi/lo)
__device__ __half g_xh [(long long)Bsz * Nq * Cdim];
__device__ __half g_yh [(long long)Bsz * My * Cdim];
__device__ __half g_Wqkvh[(long long)3 * Cdim * Cdim];
__device__ __half g_Wqkvl[(long long)3 * Cdim * Cdim];
__device__ __half g_Wkvh [(long long)2 * Cdim * Cdim];
__device__ __half g_Wkvl [(long long)2 * Cdim * Cdim];
__device__ __half g_Wph  [(long long)Cdim * Cdim];
__device__ __half g_Wpl  [(long long)Cdim * Cdim];
__device__ __half g_Oh   [(long long)Bsz * Nq * Cdim];      // attention output (single fp16)
// attention operands (fp16: Q single, K split, V^T split)
__device__ __half g_Qs [(long long)Bsz * Hn * Nq * HDim];
__device__ __half g_Kh [(long long)Bsz * Hn * Sk * HDim];
__device__ __half g_Kl [(long long)Bsz * Hn * Sk * HDim];
__device__ __half g_Vth[(long long)Bsz * Hn * HDim * Sk];   // V^T [bh][d][s]
__device__ __half g_Vtl[(long long)Bsz * Hn * HDim * Sk];

// ---------------- small PTX helpers (baseline PTX only) ----------------
__device__ __forceinline__ uint32_t smem_u32(const void* p) {
    uint32_t a;
    asm("{ .reg .u64 t; cvta.to.shared.u64 t, %1; cvt.u32.u64 %0, t; }" : "=r"(a) : "l"(p));
    return a;
}
__device__ __forceinline__ void cp16(uint32_t dst, const void* src) {
    asm volatile("cp.async.cg.shared.global [%0], [%1], 16;" :: "r"(dst), "l"(src));
}
#define CP_COMMIT()  asm volatile("cp.async.commit_group;" ::: "memory")
#define CP_WAIT(n)   asm volatile("cp.async.wait_group %0;" :: "n"(n) : "memory")

__device__ __forceinline__ void mma_fp16(float d[4], const uint32_t a[4], const uint32_t b[2]) {
    asm volatile(
        "mma.sync.aligned.m16n8k16.row.col.f32.f16.f16.f32 "
        "{%0,%1,%2,%3}, {%4,%5,%6,%7}, {%8,%9}, {%0,%1,%2,%3};"
        : "+f"(d[0]), "+f"(d[1]), "+f"(d[2]), "+f"(d[3])
        : "r"(a[0]), "r"(a[1]), "r"(a[2]), "r"(a[3]), "r"(b[0]), "r"(b[1]));
}
__device__ __forceinline__ void split_write_h(float v, __half* h, __half* l, long long idx) {
    const __half hb = __float2half(v);
    h[idx] = hb;
    l[idx] = __float2half(v - __half2float(hb));
}
__device__ __forceinline__ uint32_t pack_hf2(float a, float b) {
    __half2 v; v.x = __float2half(a); v.y = __float2half(b);
    return *(uint32_t*)&v;
}

// ---------------- 128x128 fp16 2-product HMMA GEMM core (R14-proven, dbl-buffered) --
constexpr int MM_STRIDE_B = 80;
constexpr int MM_ARR_B    = 128 * MM_STRIDE_B;   // 10240
constexpr int MM_BUF_B    = 3 * MM_ARR_B;        // A, Bh, Bl = 30720
constexpr int MM_SMEM_B   = 2 * MM_BUF_B;        // 61440

constexpr int QKV_COLT = 3 * Cdim / 128;     // 36
constexpr int QKV_CTAS = QKV_COLT * (Bsz * Nq / 128);   // 1152
constexpr int KV_COLT  = 2 * Cdim / 128;     // 24
constexpr int FUSED_CTAS = QKV_CTAS + KV_COLT * (Bsz * My / 128);  // 1344

#define MM_BODY(AP, BhP, BlP)                                                               \
    const int s0   = tid * 2;                                                               \
    const int row_s0 = s0 >> 2,  q_s0 = s0 & 3;                                             \
    const int row_s1 = (s0 + 1) >> 2, q_s1 = (s0 + 1) & 3;                                  \
    auto stage = [&](int c, int buf) {                                                      \
        const long long k0 = (long long)c * 32;                                             \
        const uint32_t db = sbase + buf * MM_BUF_B;                                         \
        {                                                                                   \
            const long long ga = (long long)(row0 + row_s0) * Cdim + k0 + q_s0 * 8;         \
            const long long gb = (long long)(col0 + row_s0) * Cdim + k0 + q_s0 * 8;         \
            const uint32_t  so = row_s0 * MM_STRIDE_B + q_s0 * 16;                          \
            cp16(db + 0 * MM_ARR_B + so, (AP) + ga);                                        \
            cp16(db + 1 * MM_ARR_B + so, (BhP) + gb);                                       \
            cp16(db + 2 * MM_ARR_B + so, (BlP) + gb);                                       \
        }                                                                                   \
        {                                                                                   \
            const long long ga = (long long)(row0 + row_s1) * Cdim + k0 + q_s1 * 8;         \
            const long long gb = (long long)(col0 + row_s1) * Cdim + k0 + q_s1 * 8;         \
            const uint32_t  so = row_s1 * MM_STRIDE_B + q_s1 * 16;                          \
            cp16(db + 0 * MM_ARR_B + so, (AP) + ga);                                        \
            cp16(db + 1 * MM_ARR_B + so, (BhP) + gb);                                       \
            cp16(db + 2 * MM_ARR_B + so, (BlP) + gb);                                       \
        }                                                                                   \
    };                                                                                      \
    float acc[4][4][4];                                                                     \
    _Pragma("unroll")                                                                       \
    for (int i = 0; i < 4; i++)                                                             \
        _Pragma("unroll")                                                                   \
        for (int j = 0; j < 4; j++)                                                         \
            _Pragma("unroll")                                                               \
            for (int r = 0; r < 4; r++) acc[i][j][r] = 0.f;                                 \
    constexpr int nch = Cdim / 32;                                                          \
    stage(0, 0);                                                                            \
    CP_COMMIT();                                                                            \
    for (int c = 0; c < nch; c++) {                                                         \
        if (c + 1 < nch) { stage(c + 1, (c + 1) & 1); CP_COMMIT(); CP_WAIT(1); }            \
        else             { CP_WAIT(0); }                                                    \
        __syncthreads();                                                                    \
        const char* bp = smem + (c & 1) * MM_BUF_B;                                         \
        const char* pA  = bp;                                                               \
        const char* pBh = bp + 1 * MM_ARR_B;                                                \
        const char* pBl = bp + 2 * MM_ARR_B;                                                \
        _Pragma("unroll")                                                                   \
        for (int kk = 0; kk < 2; kk++) {                                                    \
            const int cbyte = (kk * 16 + 2 * tg) * 2;                                       \
            uint32_t av[4][4], bh[4][2], bl[4][2];                                          \
            _Pragma("unroll")                                                               \
            for (int mt = 0; mt < 4; mt++) {                                                \
                const int r = wm + mt * 16 + g;                                             \
                av[mt][0] = *(const uint32_t*)(pA + r * MM_STRIDE_B + cbyte);               \
                av[mt][1] = *(const uint32_t*)(pA + (r + 8) * MM_STRIDE_B + cbyte);         \
                av[mt][2] = *(const uint32_t*)(pA + r * MM_STRIDE_B + cbyte + 16);          \
                av[mt][3] = *(const uint32_t*)(pA + (r + 8) * MM_STRIDE_B + cbyte + 16);    \
            }                                                                               \
            _Pragma("unroll")                                                               \
            for (int nt = 0; nt < 4; nt++) {                                                \
                const int n = wn + nt * 8 + g;                                              \
                bh[nt][0] = *(const uint32_t*)(pBh + n * MM_STRIDE_B + cbyte);              \
                bh[nt][1] = *(const uint32_t*)(pBh + n * MM_STRIDE_B + cbyte + 16);         \
                bl[nt][0] = *(const uint32_t*)(pBl + n * MM_STRIDE_B + cbyte);              \
                bl[nt][1] = *(const uint32_t*)(pBl + n * MM_STRIDE_B + cbyte + 16);         \
            }                                                                               \
            _Pragma("unroll")                                                               \
            for (int mt = 0; mt < 4; mt++)                                                  \
                _Pragma("unroll")                                                           \
                for (int nt = 0; nt < 4; nt++) {                                            \
                    mma_fp16(acc[mt][nt], av[mt], bh[nt]);                                  \
                    mma_fp16(acc[mt][nt], av[mt], bl[nt]);                                  \
                }                                                                           \
        }                                                                                   \
        __syncthreads();                                                                    \
    }

// ---- fused QKV + KV weight GEMM ----
__global__ __launch_bounds__(256, 2)
void mma_gemm_fused(const __half* __restrict__ xh,
                    const __half* __restrict__ Wqh, const __half* __restrict__ Wql,
                    float* __restrict__ Cq,
                    const __half* __restrict__ yh,
                    const __half* __restrict__ Wkh, const __half* __restrict__ Wkl,
                    float* __restrict__ Ck)
{
    extern __shared__ char smem[];
    const uint32_t sbase = smem_u32(smem);

    const int tid  = threadIdx.x;
    const int lane = tid & 31;
    const int wid  = tid >> 5;
    const int wm   = (wid >> 2) * 64;
    const int wn   = (wid & 3) * 32;
    const int g    = lane >> 2;
    const int tg   = lane & 3;

    const int bid = blockIdx.x;
    const __half *A, *Bh, *Bl;
    float* C;
    int row0, col0, ldc;
    if (bid < QKV_CTAS) {
        A = xh; Bh = Wqh; Bl = Wql; C = Cq;
        row0 = (bid / QKV_COLT) * 128;
        col0 = (bid % QKV_COLT) * 128;
        ldc  = 3 * Cdim;
    } else {
        const int b2 = bid - QKV_CTAS;
        A = yh; Bh = Wkh; Bl = Wkl; C = Ck;
        row0 = (b2 / KV_COLT) * 128;
        col0 = (b2 % KV_COLT) * 128;
        ldc  = 2 * Cdim;
    }

    MM_BODY(A, Bh, Bl)

    #pragma unroll
    for (int nt = 0; nt < 4; nt++) {
        const int col = col0 + wn + nt * 8 + 2 * tg;
        #pragma unroll
        for (int mt = 0; mt < 4; mt++) {
            const int r = row0 + wm + mt * 16 + g;
            float2 v0, v1;
            v0.x = acc[mt][nt][0]; v0.y = acc[mt][nt][1];
            v1.x = acc[mt][nt][2]; v1.y = acc[mt][nt][3];
            *(float2*)(C + (long long)r * ldc + col)       = v0;
            *(float2*)(C + (long long)(r + 8) * ldc + col) = v1;
        }
    }
}

// ---- proj GEMM (bias): A = attention O (single fp16), B = Wproj split ----
__global__ __launch_bounds__(256, 2)
void mma_gemm_proj(const __half* __restrict__ Ap,
                   const __half* __restrict__ Bhp, const __half* __restrict__ Blp,
                   float* __restrict__ C, const float* __restrict__ bias)
{
    extern __shared__ char smem[];
    const uint32_t sbase = smem_u32(smem);

    const int tid  = threadIdx.x;
    const int lane = tid & 31;
    const int wid  = tid >> 5;
    const int row0 = blockIdx.y * 128;
    const int col0 = blockIdx.x * 128;
    const int wm   = (wid >> 2) * 64;
    const int wn   = (wid & 3) * 32;
    const int g    = lane >> 2;
    const int tg   = lane & 3;

    MM_BODY(Ap, Bhp, Blp)

    #pragma unroll
    for (int nt = 0; nt < 4; nt++) {
        const int col = col0 + wn + nt * 8 + 2 * tg;
        const float b0 = bias[col], b1 = bias[col + 1];
        #pragma unroll
        for (int mt = 0; mt < 4; mt++) {
            const int r = row0 + wm + mt * 16 + g;
            float2 v0, v1;
            v0.x = acc[mt][nt][0] + b0; v0.y = acc[mt][nt][1] + b1;
            v1.x = acc[mt][nt][2] + b0; v1.y = acc[mt][nt][3] + b1;
            *(float2*)(C + (long long)r * Cdim + col)       = v0;
            *(float2*)(C + (long long)(r + 8) * Cdim + col) = v1;
        }
    }
}

// ---------------- fused attention v4: fp16, S 2-product, PV 2-product ----------------
// Q single fp16 (held); K split fp16 double-buffered; V^T split fp16; P single fp16
// with logits shifted by -SHIFT (cancels in normalization).
constexpr int FA_NIT  = Sk / 64;                 // 40
constexpr int F4_Q    = 0;                        // Q: 128 x 272B (fp16 single)
constexpr int F4_K0   = 34816;                    // 2 K buffers, each hi 64x272 + lo
constexpr int F4_KBUF = 34816;
constexpr int F4_KLOF = 17408;
constexpr int F4_VH   = 104448;                   // V^T hi: 128 x 144B
constexpr int F4_VL   = 122880;
constexpr int F4_YB   = 141312;                   // yb: 512 floats
constexpr int FA_SMEM = 143360;

__global__ __launch_bounds__(256, 1)
void fused_attn(const __half* __restrict__ Qs,
                const __half* __restrict__ Kh, const __half* __restrict__ Kl,
                const __half* __restrict__ Vth, const __half* __restrict__ Vtl,
                const float* __restrict__ ytw,
                __half* __restrict__ Oh)
{
    extern __shared__ char smem[];
    const uint32_t sb = smem_u32(smem);

    const int z  = blockIdx.y;
    const int q0 = blockIdx.x * 128;
    const int b  = z / Hn;
    const int h  = z % Hn;

    const int tid  = threadIdx.x;
    const int lane = tid & 31;
    const int wid  = tid >> 5;            // 0..7
    const int g    = lane >> 2;
    const int tg   = lane & 3;
    const int wm   = wid * 16;

    const __half* Qp  = Qs + (long long)z * Nq * HDim;
    const __half* Khp = Kh + (long long)z * Sk * HDim;
    const __half* Klp = Kl + (long long)z * Sk * HDim;
    const __half* Vhp = Vth + (long long)z * HDim * Sk;
    const __half* Vlp = Vtl + (long long)z * HDim * Sk;

    // y bias, pre-shifted
    float* sYB = (float*)(smem + F4_YB);
    #pragma unroll
    for (int j = 0; j < 2; j++) {
        const int i = tid + j * 256;
        sYB[i] = logf(fmaxf(ytw[b * My + i], 1e-4f)) - SHIFT;
    }

    // group 1: Q (128 rows x 16 segs, single fp16)
    #pragma unroll
    for (int j = 0; j < 8; j++) {
        const int id = tid + j * 256, r = id >> 4, c = id & 15;
        cp16(sb + F4_Q + r * 272 + c * 16, Qp + (long long)(q0 + r) * HDim + c * 8);
    }
    CP_COMMIT();
    // group 2: K(0) into buffer 0 (split)
    #pragma unroll
    for (int j = 0; j < 4; j++) {
        const int id = tid + j * 256, r = id >> 4, c = id & 15;
        cp16(sb + F4_K0 +           r * 272 + c * 16, Khp + (long long)r * HDim + c * 8);
        cp16(sb + F4_K0 + F4_KLOF + r * 272 + c * 16, Klp + (long long)r * HDim + c * 8);
    }
    CP_COMMIT();

    float oacc[16][4];
    #pragma unroll
    for (int i = 0; i < 16; i++)
        #pragma unroll
        for (int r = 0; r < 4; r++) oacc[i][r] = 0.f;
    float rowsum0 = 0.f, rowsum1 = 0.f;

    for (int it = 0; it < FA_NIT; it++) {
        __syncthreads();

        // group: K(it+1) prefetch
        if (it + 1 < FA_NIT) {
            const uint32_t kb = sb + F4_K0 + ((it + 1) & 1) * F4_KBUF;
            const int sblk = (it + 1) * 64;
            #pragma unroll
            for (int j = 0; j < 4; j++) {
                const int id = tid + j * 256, r = id >> 4, c = id & 15;
                cp16(kb +           r * 272 + c * 16, Khp + (long long)(sblk + r) * HDim + c * 8);
                cp16(kb + F4_KLOF + r * 272 + c * 16, Klp + (long long)(sblk + r) * HDim + c * 8);
            }
        }
        CP_COMMIT();
        // group: V(it) (split)
        #pragma unroll
        for (int j = 0; j < 4; j++) {
            const int id = tid + j * 256, d = id >> 3, c = id & 7;
            cp16(sb + F4_VH + d * 144 + c * 16, Vhp + (long long)d * Sk + it * 64 + c * 8);
            cp16(sb + F4_VL + d * 144 + c * 16, Vlp + (long long)d * Sk + it * 64 + c * 8);
        }
        CP_COMMIT();

        CP_WAIT(2);                        // K(it) (and Q on it=0) ready
        __syncthreads();

        // ---- S phase: S[16 x 64] = Q K(it)^T (fp16, 2 products) ----
        const uint32_t kcur = sb + F4_K0 + (it & 1) * F4_KBUF;
        float sacc[8][4];
        #pragma unroll
        for (int i = 0; i < 8; i++)
            #pragma unroll
            for (int r = 0; r < 4; r++) sacc[i][r] = 0.f;

        #pragma unroll
        for (int kk = 0; kk < 8; kk++) {
            const int cb = kk * 32 + tg * 4;
            uint32_t q_[4], kh_[8][2], kl_[8][2];
            {
                const char* p = smem + F4_Q + (wm + g) * 272 + cb;
                q_[0] = *(const uint32_t*)(p);
                q_[1] = *(const uint32_t*)(p + 8 * 272);
                q_[2] = *(const uint32_t*)(p + 16);
                q_[3] = *(const uint32_t*)(p + 8 * 272 + 16);
            }
            #pragma unroll
            for (int nt = 0; nt < 8; nt++) {
                const char* p = (const char*)smem + (kcur - sb) + (nt * 8 + g) * 272 + cb;
                kh_[nt][0] = *(const uint32_t*)(p);
                kh_[nt][1] = *(const uint32_t*)(p + 16);
                kl_[nt][0] = *(const uint32_t*)(p + F4_KLOF);
                kl_[nt][1] = *(const uint32_t*)(p + F4_KLOF + 16);
            }
            #pragma unroll
            for (int nt = 0; nt < 8; nt++) {
                mma_fp16(sacc[nt], q_, kh_[nt]);
                mma_fp16(sacc[nt], q_, kl_[nt]);
            }
        }

        // ---- exp (+scale +bias -SHIFT) -> PV A-fragments (single fp16) ----
        uint32_t ph_[4][4];
        #pragma unroll
        for (int nt = 0; nt < 8; nt++) {
            const int col0 = nt * 8 + 2 * tg;
            const int gc   = it * 64 + col0;
            float b0 = -SHIFT, b1 = -SHIFT;
            if (gc >= Nq) { b0 = sYB[gc - Nq]; b1 = sYB[gc - Nq + 1]; }
            const float p0 = __expf(sacc[nt][0] * SCALE + b0);
            const float p1 = __expf(sacc[nt][1] * SCALE + b1);
            const float p2 = __expf(sacc[nt][2] * SCALE + b0);
            const float p3 = __expf(sacc[nt][3] * SCALE + b1);
            rowsum0 += p0 + p1;
            rowsum1 += p2 + p3;
            const int j  = nt >> 1;
            const int rb = (nt & 1) * 2;
            ph_[j][rb + 0] = pack_hf2(p0, p1);
            ph_[j][rb + 1] = pack_hf2(p2, p3);
        }

        CP_WAIT(1);                        // V(it) ready
        __syncthreads();

        // ---- PV phase: O[16 x 128] += P V(it) (fp16, 2 products) ----
        #pragma unroll
        for (int j = 0; j < 4; j++) {
            const int cb = j * 32 + tg * 4;
            #pragma unroll
            for (int nt = 0; nt < 16; nt++) {
                uint32_t vh_[2], vl_[2];
                const char* p = smem + F4_VH + (nt * 8 + g) * 144 + cb;
                vh_[0] = *(const uint32_t*)(p);
                vh_[1] = *(const uint32_t*)(p + 16);
                vl_[0] = *(const uint32_t*)(p + (F4_VL - F4_VH));
                vl_[1] = *(const uint32_t*)(p + (F4_VL - F4_VH) + 16);
                mma_fp16(oacc[nt], ph_[j], vh_);
                mma_fp16(oacc[nt], ph_[j], vl_);
            }
        }
    }

    // ---- rowsum reduce within tg quad ----
    rowsum0 += __shfl_xor_sync(0xffffffffu, rowsum0, 1);
    rowsum0 += __shfl_xor_sync(0xffffffffu, rowsum0, 2);
    rowsum1 += __shfl_xor_sync(0xffffffffu, rowsum1, 1);
    rowsum1 += __shfl_xor_sync(0xffffffffu, rowsum1, 2);
    const float inv0 = 1.f / rowsum0;
    const float inv1 = 1.f / rowsum1;

    // ---- epilogue: normalize (shift cancels), write single fp16 O ----
    const int r = wm + g;
    #pragma unroll
    for (int nt = 0; nt < 16; nt++) {
        const int col = nt * 8 + 2 * tg;
        const long long o0 = ((long long)b * Nq + q0 + r) * Cdim + h * HDim + col;
        const long long o1 = o0 + 8LL * Cdim;
        __half2 v0, v1;
        v0.x = __float2half(oacc[nt][0] * inv0);
        v0.y = __float2half(oacc[nt][1] * inv0);
        v1.x = __float2half(oacc[nt][2] * inv1);
        v1.y = __float2half(oacc[nt][3] * inv1);
        *(__half2*)(Oh + o0) = v0;
        *(__half2*)(Oh + o1) = v1;
    }
}

// ---------------- fp32 -> single fp16, two tensors in one launch ----------------
__global__ void cvt_single2(const float* __restrict__ s1, __half* __restrict__ h1, long long n1,
                            const float* __restrict__ s2, __half* __restrict__ h2, long long n2)
{
    long long i = ((long long)blockIdx.x * blockDim.x + threadIdx.x) * 4;
    const float* src; __half* h;
    if (i < n1) { src = s1; h = h1; }
    else        { i -= n1; if (i >= n2) return; src = s2; h = h2; }
    const float4 v = *(const float4*)(src + i);
    __half hb[4];
    hb[0] = __float2half(v.x); hb[1] = __float2half(v.y);
    hb[2] = __float2half(v.z); hb[3] = __float2half(v.w);
    *(uint2*)(h + i) = *(uint2*)hb;
}

// ---------------- fp32 [K][N] -> split fp16 transposed [N][K]; 2 weights packed ----
constexpr int WQ_BLKS = (3 * Cdim / 32) * (Cdim / 32);   // 6912
constexpr int WK_BLKS = (2 * Cdim / 32) * (Cdim / 32);   // 4608

__global__ void cvt_split_T2(const float* __restrict__ W1, __half* __restrict__ h1,
                             __half* __restrict__ l1,
                             const float* __restrict__ W2, __half* __restrict__ h2,
                             __half* __restrict__ l2)
{
    __shared__ float tile[32][33];
    const int tid = threadIdx.x;
    const int tx = tid & 31;
    const int ty = tid >> 5;

    const float* W; __half *h, *l;
    int N, n0, k0;
    int bid = blockIdx.x;
    if (bid < WQ_BLKS) {
        W = W1; h = h1; l = l1; N = 3 * Cdim;
        n0 = (bid % (N / 32)) * 32;  k0 = (bid / (N / 32)) * 32;
    } else {
        bid -= WQ_BLKS;
        W = W2; h = h2; l = l2; N = 2 * Cdim;
        n0 = (bid % (N / 32)) * 32;  k0 = (bid / (N / 32)) * 32;
    }

    #pragma unroll
    for (int i = ty; i < 32; i += 8)
        tile[i][tx] = W[(long long)(k0 + i) * N + n0 + tx];
    __syncthreads();
    #pragma unroll
    for (int i = ty; i < 32; i += 8) {
        const float v = tile[tx][i];
        const __half hb = __float2half(v);
        const __half lb = __float2half(v - __half2float(hb));
        const long long o = (long long)(n0 + i) * Cdim + k0 + tx;
        h[o] = hb; l[o] = lb;
    }
}

// ---------------- single-weight transposed split fp16 (Wproj) ----------------
__global__ void cvt_split_T(const float* __restrict__ W, __half* __restrict__ h,
                            __half* __restrict__ l, int K, int N)
{
    __shared__ float tile[32][33];
    const int k0 = blockIdx.y * 32;
    const int n0 = blockIdx.x * 32;
    const int tx = threadIdx.x;
    const int ty = threadIdx.y;
    #pragma unroll
    for (int i = ty; i < 32; i += 8)
        tile[i][tx] = W[(long long)(k0 + i) * N + n0 + tx];
    __syncthreads();
    #pragma unroll
    for (int i = ty; i < 32; i += 8) {
        const float v = tile[tx][i];
        const __half hb = __float2half(v);
        const __half lb = __float2half(v - __half2float(hb));
        const long long o = (long long)(n0 + i) * K + k0 + tx;
        h[o] = hb; l[o] = lb;
    }
}

// ---------------- V: fp32 [bh][s][d] -> split fp16 transposed [bh][d][s] ----------
__global__ void v_transpose_split(const float* __restrict__ Vb,
                                  __half* __restrict__ Vth,
                                  __half* __restrict__ Vtl)
{
    __shared__ float tile[32][33];
    const int z  = blockIdx.z;
    const int ss0 = blockIdx.x * 32;
    const int dd0 = blockIdx.y * 32;
    const int tx = threadIdx.x;
    const int ty = threadIdx.y;
    const long long ib = (long long)z * Sk * HDim;
    const long long ob = (long long)z * HDim * Sk;
    #pragma unroll
    for (int i = ty; i < 32; i += 8)
        tile[i][tx] = Vb[ib + (long long)(ss0 + i) * HDim + dd0 + tx];
    __syncthreads();
    #pragma unroll
    for (int i = ty; i < 32; i += 8) {
        const float v = tile[tx][i];
        const __half hb = __float2half(v);
        const __half lb = __float2half(v - __half2float(hb));
        const long long o = ob + (long long)(dd0 + i) * Sk + ss0 + tx;
        Vth[o] = hb; Vtl[o] = lb;
    }
}

// ---------------- warp reduction helpers ----------------
__device__ __forceinline__ float warpSum(float v) {
    #pragma unroll
    for (int o = 16; o > 0; o >>= 1) v += __shfl_xor_sync(0xffffffffu, v, o);
    return v;
}

// ---------------- QKV postprocess: RMSNorm + RoPE -> fp16 Q(single), K(split); fp32 V
__global__ void qkv_post(const float* __restrict__ qkv, const float* __restrict__ pos,
                         const float* __restrict__ qw, const float* __restrict__ kw,
                         __half* __restrict__ Qs,
                         __half* __restrict__ Kh, __half* __restrict__ Kl,
                         float* __restrict__ Vb)
{
    const int idx = blockIdx.x;
    const int h  = idx % Hn;
    const int bn = idx / Hn;
    const int n  = bn % Nq;
    const int b  = bn / Nq;
    const int d  = threadIdx.x;

    const float* row = qkv + (long long)bn * (3 * Cdim);
    const float qv = row[h * HDim + d];
    const float kv = row[Cdim + h * HDim + d];
    const float vv = row[2 * Cdim + h * HDim + d];

    __shared__ float sred[8];
    __shared__ float qs[HDim], ks[HDim];

    const float sq = warpSum(qv * qv);
    const float sk = warpSum(kv * kv);
    const int lane = d & 31, w = d >> 5;
    if (lane == 0) { sred[w] = sq; sred[4 + w] = sk; }
    __syncthreads();
    const float sumq = sred[0] + sred[1] + sred[2] + sred[3];
    const float sumk = sred[4] + sred[5] + sred[6] + sred[7];
    const float rq = rsqrtf(sumq * (1.0f / HDim) + EPSV);
    const float rk = rsqrtf(sumk * (1.0f / HDim) + EPSV);
    const float qn = qw[d] * qv * rq;
    const float kn = kw[d] * kv * rk;
    qs[d] = qn; ks[d] = kn;
    __syncthreads();

    float qo = qn, ko = kn;
    if (d < RD) {
        const int j = d & 31;
        const float c = pos[(n * 32 + j) * 2 + 0];
        const float s = pos[(n * 32 + j) * 2 + 1];
        if (d < RD / 2) { qo = qs[d] * c - qs[d + 32] * s;  ko = ks[d] * c - ks[d + 32] * s; }
        else            { qo = qs[d - 32] * s + qs[d] * c;  ko = ks[d - 32] * s + ks[d] * c; }
    }
    const long long qi = (((long long)(b * Hn + h)) * Nq + n) * HDim + d;
    const long long ki = (((long long)(b * Hn + h)) * Sk + n) * HDim + d;
    Qs[qi] = __float2half(qo);
    split_write_h(ko, Kh, Kl, ki);
    Vb[ki] = vv;
}

// ---------------- KV(y) postprocess ----------------
__global__ void kv_post(const float* __restrict__ kvr, const float* __restrict__ kw,
                        __half* __restrict__ Kh, __half* __restrict__ Kl,
                        float* __restrict__ Vb)
{
    const int idx = blockIdx.x;
    const int h  = idx % Hn;
    const int bm = idx / Hn;
    const int m  = bm % My;
    const int b  = bm / My;
    const int d  = threadIdx.x;

    const float* row = kvr + (long long)bm * (2 * Cdim);
    const float kv = row[h * HDim + d];
    const float vv = row[Cdim + h * HDim + d];

    __shared__ float sred[4];
    const float sk = warpSum(kv * kv);
    if ((d & 31) == 0) sred[d >> 5] = sk;
    __syncthreads();
    const float sumk = sred[0] + sred[1] + sred[2] + sred[3];
    const float rk = rsqrtf(sumk * (1.0f / HDim) + EPSV);
    const float kn = kw[d] * kv * rk;

    const long long ki = (((long long)(b * Hn + h)) * Sk + (Nq + m)) * HDim + d;
    split_write_h(kn, Kh, Kl, ki);
    Vb[ki] = vv;
}

// ---------------- launch ----------------
extern "C" void kernel_launch(void* const* d_in, const int* in_sizes, int n_in,
                              void* d_out, int out_size)
{
    const float* x    = (const float*)d_in[0];
    const float* y    = (const float*)d_in[1];
    const float* pos  = (const float*)d_in[2];
    const float* ytw  = (const float*)d_in[3];
    const float* Wqkv = (const float*)d_in[4];
    const float* Wkv  = (const float*)d_in[5];
    const float* qw   = (const float*)d_in[6];
    const float* kw   = (const float*)d_in[7];
    const float* Wproj= (const float*)d_in[8];
    const float* bproj= (const float*)d_in[9];
    float* out = (float*)d_out;

    float *qkv, *kvr, *Vb;
    cudaGetSymbolAddress((void**)&qkv, g_qkv);
    cudaGetSymbolAddress((void**)&kvr, g_kvr);
    cudaGetSymbolAddress((void**)&Vb,  g_Vb);

    __half *xh,*yh,*Wqh,*Wql,*Wkh,*Wkl,*Wph,*Wpl,*Oh;
    __half *Qs,*Kh,*Kl,*Vth,*Vtl;
    cudaGetSymbolAddress((void**)&xh, g_xh);
    cudaGetSymbolAddress((void**)&yh, g_yh);
    cudaGetSymbolAddress((void**)&Wqh, g_Wqkvh); cudaGetSymbolAddress((void**)&Wql, g_Wqkvl);
    cudaGetSymbolAddress((void**)&Wkh, g_Wkvh);  cudaGetSymbolAddress((void**)&Wkl, g_Wkvl);
    cudaGetSymbolAddress((void**)&Wph, g_Wph);   cudaGetSymbolAddress((void**)&Wpl, g_Wpl);
    cudaGetSymbolAddress((void**)&Oh, g_Oh);
    cudaGetSymbolAddress((void**)&Qs, g_Qs);
    cudaGetSymbolAddress((void**)&Kh, g_Kh);     cudaGetSymbolAddress((void**)&Kl, g_Kl);
    cudaGetSymbolAddress((void**)&Vth, g_Vth);   cudaGetSymbolAddress((void**)&Vtl, g_Vtl);

    cudaFuncSetAttribute(mma_gemm_fused, cudaFuncAttributeMaxDynamicSharedMemorySize, MM_SMEM_B);
    cudaFuncSetAttribute(mma_gemm_proj,  cudaFuncAttributeMaxDynamicSharedMemorySize, MM_SMEM_B);
    cudaFuncSetAttribute(fused_attn, cudaFuncAttributeMaxDynamicSharedMemorySize, FA_SMEM);

    // 0) conversions
    const long long nx = (long long)Bsz * Nq * Cdim;
    const long long ny = (long long)Bsz * My * Cdim;
    cvt_single2<<<(int)(((nx + ny) / 4 + 255) / 256), 256>>>(x, xh, nx, y, yh, ny);
    cvt_split_T2<<<WQ_BLKS + WK_BLKS, 256>>>(Wqkv, Wqh, Wql, Wkv, Wkh, Wkl);
    cvt_split_T<<<dim3(Cdim / 32, Cdim / 32), dim3(32, 8)>>>(Wproj, Wph, Wpl, Cdim, Cdim);

    // 1+2) fused QKV + KV weight GEMM (fp16 2-product)
    mma_gemm_fused<<<FUSED_CTAS, 256, MM_SMEM_B>>>(
        xh, Wqh, Wql, qkv, yh, Wkh, Wkl, kvr);

    // 3) postprocess (fp16 attention operands)
    qkv_post<<<Bsz * Nq * Hn, HDim>>>(qkv, pos, qw, kw, Qs, Kh, Kl, Vb);
    kv_post<<<Bsz * My * Hn, HDim>>>(kvr, kw, Kh, Kl, Vb);
    v_transpose_split<<<dim3(Sk / 32, HDim / 32, Bsz * Hn), dim3(32, 8)>>>(Vb, Vth, Vtl);

    // 4-6) fused attention v4 (fp16, 4 products total) -> single fp16 O
    fused_attn<<<dim3(Nq / 128, Bsz * Hn), 256, FA_SMEM>>>(
        Qs, Kh, Kl, Vth, Vtl, ytw, Oh);

    // 7) out = O @ Wproj + bproj (fp16 2-product)
    mma_gemm_proj<<<dim3(Cdim / 128, Bsz * Nq / 128), 256, MM_SMEM_B>>>(
        Oh, Wph, Wpl, out, bproj);
}

// round 17
// speedup vs baseline: 1.3827x; 1.2484x over previous
#include <cuda_runtime.h>
#include <cuda_bf16.h>
#include <cuda_fp16.h>
#include <math.h>
#include <cstdint>

// ---------------- problem constants ----------------
constexpr int Bsz  = 2;
constexpr int Nq   = 2048;
constexpr int My   = 512;
constexpr int Cdim = 1536;
constexpr int Hn   = 12;
constexpr int HDim = 128;          // Cdim / Hn
constexpr int RD   = 64;
constexpr int Sk   = Nq + My;      // 2560
constexpr float EPSV  = 1e-6f;
constexpr float SCALE = 0.08838834764831845f;   // 1/sqrt(128)
constexpr float SHIFT = 5.545177444479562f;     // 8*ln2; cancels in softmax

// ---------------- scratch (static device arrays; no allocs allowed) ----------------
__device__ float g_qkv [(long long)Bsz * Nq * 3 * Cdim];
__device__ float g_kvr [(long long)Bsz * My * 2 * Cdim];
__device__ float g_Vb  [(long long)Bsz * Hn * Sk * HDim];   // V fp32 [bh][s][d]

// fp16 operands (all single-precision fp16 for weight GEMMs)
__device__ __half g_xh [(long long)Bsz * Nq * Cdim];
__device__ __half g_yh [(long long)Bsz * My * Cdim];
__device__ __half g_Wqkvh[(long long)3 * Cdim * Cdim];
__device__ __half g_Wkvh [(long long)2 * Cdim * Cdim];
__device__ __half g_Wph  [(long long)Cdim * Cdim];
__device__ __half g_Oh   [(long long)Bsz * Nq * Cdim];      // attention output (single fp16)
// attention operands (fp16: Q single, K split, V^T split) — R16-proven
__device__ __half g_Qs [(long long)Bsz * Hn * Nq * HDim];
__device__ __half g_Kh [(long long)Bsz * Hn * Sk * HDim];
__device__ __half g_Kl [(long long)Bsz * Hn * Sk * HDim];
__device__ __half g_Vth[(long long)Bsz * Hn * HDim * Sk];   // V^T [bh][d][s]
__device__ __half g_Vtl[(long long)Bsz * Hn * HDim * Sk];

// ---------------- small PTX helpers (baseline PTX only) ----------------
__device__ __forceinline__ uint32_t smem_u32(const void* p) {
    uint32_t a;
    asm("{ .reg .u64 t; cvta.to.shared.u64 t, %1; cvt.u32.u64 %0, t; }" : "=r"(a) : "l"(p));
    return a;
}
__device__ __forceinline__ void cp16(uint32_t dst, const void* src) {
    asm volatile("cp.async.cg.shared.global [%0], [%1], 16;" :: "r"(dst), "l"(src));
}
#define CP_COMMIT()  asm volatile("cp.async.commit_group;" ::: "memory")
#define CP_WAIT(n)   asm volatile("cp.async.wait_group %0;" :: "n"(n) : "memory")

__device__ __forceinline__ void mma_fp16(float d[4], const uint32_t a[4], const uint32_t b[2]) {
    asm volatile(
        "mma.sync.aligned.m16n8k16.row.col.f32.f16.f16.f32 "
        "{%0,%1,%2,%3}, {%4,%5,%6,%7}, {%8,%9}, {%0,%1,%2,%3};"
        : "+f"(d[0]), "+f"(d[1]), "+f"(d[2]), "+f"(d[3])
        : "r"(a[0]), "r"(a[1]), "r"(a[2]), "r"(a[3]), "r"(b[0]), "r"(b[1]));
}
__device__ __forceinline__ void split_write_h(float v, __half* h, __half* l, long long idx) {
    const __half hb = __float2half(v);
    h[idx] = hb;
    l[idx] = __float2half(v - __half2float(hb));
}
__device__ __forceinline__ uint32_t pack_hf2(float a, float b) {
    __half2 v; v.x = __float2half(a); v.y = __float2half(b);
    return *(uint32_t*)&v;
}

// ---------------- 128x128 plain-fp16 HMMA GEMM core (1 product) ----------------
constexpr int MM_STRIDE_B = 80;
constexpr int MM_ARR_B    = 128 * MM_STRIDE_B;   // 10240
constexpr int MM_BUF_B    = 2 * MM_ARR_B;        // A, B = 20480
constexpr int MM_SMEM_B   = 2 * MM_BUF_B;        // 40960

constexpr int QKV_COLT = 3 * Cdim / 128;     // 36
constexpr int QKV_CTAS = QKV_COLT * (Bsz * Nq / 128);   // 1152
constexpr int KV_COLT  = 2 * Cdim / 128;     // 24
constexpr int FUSED_CTAS = QKV_CTAS + KV_COLT * (Bsz * My / 128);  // 1344

#define MM_BODY(AP, BP)                                                                     \
    const int s0   = tid * 2;                                                               \
    const int row_s0 = s0 >> 2,  q_s0 = s0 & 3;                                             \
    const int row_s1 = (s0 + 1) >> 2, q_s1 = (s0 + 1) & 3;                                  \
    auto stage = [&](int c, int buf) {                                                      \
        const long long k0 = (long long)c * 32;                                             \
        const uint32_t db = sbase + buf * MM_BUF_B;                                         \
        {                                                                                   \
            const long long ga = (long long)(row0 + row_s0) * Cdim + k0 + q_s0 * 8;         \
            const long long gb = (long long)(col0 + row_s0) * Cdim + k0 + q_s0 * 8;         \
            const uint32_t  so = row_s0 * MM_STRIDE_B + q_s0 * 16;                          \
            cp16(db + so,            (AP) + ga);                                            \
            cp16(db + MM_ARR_B + so, (BP) + gb);                                            \
        }                                                                                   \
        {                                                                                   \
            const long long ga = (long long)(row0 + row_s1) * Cdim + k0 + q_s1 * 8;         \
            const long long gb = (long long)(col0 + row_s1) * Cdim + k0 + q_s1 * 8;         \
            const uint32_t  so = row_s1 * MM_STRIDE_B + q_s1 * 16;                          \
            cp16(db + so,            (AP) + ga);                                            \
            cp16(db + MM_ARR_B + so, (BP) + gb);                                            \
        }                                                                                   \
    };                                                                                      \
    float acc[4][4][4];                                                                     \
    _Pragma("unroll")                                                                       \
    for (int i = 0; i < 4; i++)                                                             \
        _Pragma("unroll")                                                                   \
        for (int j = 0; j < 4; j++)                                                         \
            _Pragma("unroll")                                                               \
            for (int r = 0; r < 4; r++) acc[i][j][r] = 0.f;                                 \
    constexpr int nch = Cdim / 32;                                                          \
    stage(0, 0);                                                                            \
    CP_COMMIT();                                                                            \
    for (int c = 0; c < nch; c++) {                                                         \
        if (c + 1 < nch) { stage(c + 1, (c + 1) & 1); CP_COMMIT(); CP_WAIT(1); }            \
        else             { CP_WAIT(0); }                                                    \
        __syncthreads();                                                                    \
        const char* bp = smem + (c & 1) * MM_BUF_B;                                         \
        const char* pA = bp;                                                                \
        const char* pB = bp + MM_ARR_B;                                                     \
        _Pragma("unroll")                                                                   \
        for (int kk = 0; kk < 2; kk++) {                                                    \
            const int cbyte = (kk * 16 + 2 * tg) * 2;                                       \
            uint32_t av[4][4], bv[4][2];                                                    \
            _Pragma("unroll")                                                               \
            for (int mt = 0; mt < 4; mt++) {                                                \
                const int r = wm + mt * 16 + g;                                             \
                av[mt][0] = *(const uint32_t*)(pA + r * MM_STRIDE_B + cbyte);               \
                av[mt][1] = *(const uint32_t*)(pA + (r + 8) * MM_STRIDE_B + cbyte);         \
                av[mt][2] = *(const uint32_t*)(pA + r * MM_STRIDE_B + cbyte + 16);          \
                av[mt][3] = *(const uint32_t*)(pA + (r + 8) * MM_STRIDE_B + cbyte + 16);    \
            }                                                                               \
            _Pragma("unroll")                                                               \
            for (int nt = 0; nt < 4; nt++) {                                                \
                const int n = wn + nt * 8 + g;                                              \
                bv[nt][0] = *(const uint32_t*)(pB + n * MM_STRIDE_B + cbyte);               \
                bv[nt][1] = *(const uint32_t*)(pB + n * MM_STRIDE_B + cbyte + 16);          \
            }                                                                               \
            _Pragma("unroll")                                                               \
            for (int mt = 0; mt < 4; mt++)                                                  \
                _Pragma("unroll")                                                           \
                for (int nt = 0; nt < 4; nt++)                                              \
                    mma_fp16(acc[mt][nt], av[mt], bv[nt]);                                  \
        }                                                                                   \
        __syncthreads();                                                                    \
    }

// ---- fused QKV + KV weight GEMM ----
__global__ __launch_bounds__(256, 2)
void mma_gemm_fused(const __half* __restrict__ xh,
                    const __half* __restrict__ Wq,
                    float* __restrict__ Cq,
                    const __half* __restrict__ yh,
                    const __half* __restrict__ Wk,
                    float* __restrict__ Ck)
{
    extern __shared__ char smem[];
    const uint32_t sbase = smem_u32(smem);

    const int tid  = threadIdx.x;
    const int lane = tid & 31;
    const int wid  = tid >> 5;
    const int wm   = (wid >> 2) * 64;
    const int wn   = (wid & 3) * 32;
    const int g    = lane >> 2;
    const int tg   = lane & 3;

    const int bid = blockIdx.x;
    const __half *A, *B;
    float* C;
    int row0, col0, ldc;
    if (bid < QKV_CTAS) {
        A = xh; B = Wq; C = Cq;
        row0 = (bid / QKV_COLT) * 128;
        col0 = (bid % QKV_COLT) * 128;
        ldc  = 3 * Cdim;
    } else {
        const int b2 = bid - QKV_CTAS;
        A = yh; B = Wk; C = Ck;
        row0 = (b2 / KV_COLT) * 128;
        col0 = (b2 % KV_COLT) * 128;
        ldc  = 2 * Cdim;
    }

    MM_BODY(A, B)

    #pragma unroll
    for (int nt = 0; nt < 4; nt++) {
        const int col = col0 + wn + nt * 8 + 2 * tg;
        #pragma unroll
        for (int mt = 0; mt < 4; mt++) {
            const int r = row0 + wm + mt * 16 + g;
            float2 v0, v1;
            v0.x = acc[mt][nt][0]; v0.y = acc[mt][nt][1];
            v1.x = acc[mt][nt][2]; v1.y = acc[mt][nt][3];
            *(float2*)(C + (long long)r * ldc + col)       = v0;
            *(float2*)(C + (long long)(r + 8) * ldc + col) = v1;
        }
    }
}

// ---- proj GEMM (bias): A = attention O (fp16), B = Wproj (fp16) ----
__global__ __launch_bounds__(256, 2)
void mma_gemm_proj(const __half* __restrict__ Ap,
                   const __half* __restrict__ Bp,
                   float* __restrict__ C, const float* __restrict__ bias)
{
    extern __shared__ char smem[];
    const uint32_t sbase = smem_u32(smem);

    const int tid  = threadIdx.x;
    const int lane = tid & 31;
    const int wid  = tid >> 5;
    const int row0 = blockIdx.y * 128;
    const int col0 = blockIdx.x * 128;
    const int wm   = (wid >> 2) * 64;
    const int wn   = (wid & 3) * 32;
    const int g    = lane >> 2;
    const int tg   = lane & 3;

    MM_BODY(Ap, Bp)

    #pragma unroll
    for (int nt = 0; nt < 4; nt++) {
        const int col = col0 + wn + nt * 8 + 2 * tg;
        const float b0 = bias[col], b1 = bias[col + 1];
        #pragma unroll
        for (int mt = 0; mt < 4; mt++) {
            const int r = row0 + wm + mt * 16 + g;
            float2 v0, v1;
            v0.x = acc[mt][nt][0] + b0; v0.y = acc[mt][nt][1] + b1;
            v1.x = acc[mt][nt][2] + b0; v1.y = acc[mt][nt][3] + b1;
            *(float2*)(C + (long long)r * Cdim + col)       = v0;
            *(float2*)(C + (long long)(r + 8) * Cdim + col) = v1;
        }
    }
}

// ---------------- fused attention v4 (R16-proven, unchanged) ----------------
constexpr int FA_NIT  = Sk / 64;                 // 40
constexpr int F4_Q    = 0;                        // Q: 128 x 272B (fp16 single)
constexpr int F4_K0   = 34816;                    // 2 K buffers, each hi 64x272 + lo
constexpr int F4_KBUF = 34816;
constexpr int F4_KLOF = 17408;
constexpr int F4_VH   = 104448;                   // V^T hi: 128 x 144B
constexpr int F4_VL   = 122880;
constexpr int F4_YB   = 141312;                   // yb: 512 floats
constexpr int FA_SMEM = 143360;

__global__ __launch_bounds__(256, 1)
void fused_attn(const __half* __restrict__ Qs,
                const __half* __restrict__ Kh, const __half* __restrict__ Kl,
                const __half* __restrict__ Vth, const __half* __restrict__ Vtl,
                const float* __restrict__ ytw,
                __half* __restrict__ Oh)
{
    extern __shared__ char smem[];
    const uint32_t sb = smem_u32(smem);

    const int z  = blockIdx.y;
    const int q0 = blockIdx.x * 128;
    const int b  = z / Hn;
    const int h  = z % Hn;

    const int tid  = threadIdx.x;
    const int lane = tid & 31;
    const int wid  = tid >> 5;
    const int g    = lane >> 2;
    const int tg   = lane & 3;
    const int wm   = wid * 16;

    const __half* Qp  = Qs + (long long)z * Nq * HDim;
    const __half* Khp = Kh + (long long)z * Sk * HDim;
    const __half* Klp = Kl + (long long)z * Sk * HDim;
    const __half* Vhp = Vth + (long long)z * HDim * Sk;
    const __half* Vlp = Vtl + (long long)z * HDim * Sk;

    float* sYB = (float*)(smem + F4_YB);
    #pragma unroll
    for (int j = 0; j < 2; j++) {
        const int i = tid + j * 256;
        sYB[i] = logf(fmaxf(ytw[b * My + i], 1e-4f)) - SHIFT;
    }

    #pragma unroll
    for (int j = 0; j < 8; j++) {
        const int id = tid + j * 256, r = id >> 4, c = id & 15;
        cp16(sb + F4_Q + r * 272 + c * 16, Qp + (long long)(q0 + r) * HDim + c * 8);
    }
    CP_COMMIT();
    #pragma unroll
    for (int j = 0; j < 4; j++) {
        const int id = tid + j * 256, r = id >> 4, c = id & 15;
        cp16(sb + F4_K0 +           r * 272 + c * 16, Khp + (long long)r * HDim + c * 8);
        cp16(sb + F4_K0 + F4_KLOF + r * 272 + c * 16, Klp + (long long)r * HDim + c * 8);
    }
    CP_COMMIT();

    float oacc[16][4];
    #pragma unroll
    for (int i = 0; i < 16; i++)
        #pragma unroll
        for (int r = 0; r < 4; r++) oacc[i][r] = 0.f;
    float rowsum0 = 0.f, rowsum1 = 0.f;

    for (int it = 0; it < FA_NIT; it++) {
        __syncthreads();

        if (it + 1 < FA_NIT) {
            const uint32_t kb = sb + F4_K0 + ((it + 1) & 1) * F4_KBUF;
            const int sblk = (it + 1) * 64;
            #pragma unroll
            for (int j = 0; j < 4; j++) {
                const int id = tid + j * 256, r = id >> 4, c = id & 15;
                cp16(kb +           r * 272 + c * 16, Khp + (long long)(sblk + r) * HDim + c * 8);
                cp16(kb + F4_KLOF + r * 272 + c * 16, Klp + (long long)(sblk + r) * HDim + c * 8);
            }
        }
        CP_COMMIT();
        #pragma unroll
        for (int j = 0; j < 4; j++) {
            const int id = tid + j * 256, d = id >> 3, c = id & 7;
            cp16(sb + F4_VH + d * 144 + c * 16, Vhp + (long long)d * Sk + it * 64 + c * 8);
            cp16(sb + F4_VL + d * 144 + c * 16, Vlp + (long long)d * Sk + it * 64 + c * 8);
        }
        CP_COMMIT();

        CP_WAIT(2);
        __syncthreads();

        const uint32_t kcur = sb + F4_K0 + (it & 1) * F4_KBUF;
        float sacc[8][4];
        #pragma unroll
        for (int i = 0; i < 8; i++)
            #pragma unroll
            for (int r = 0; r < 4; r++) sacc[i][r] = 0.f;

        #pragma unroll
        for (int kk = 0; kk < 8; kk++) {
            const int cb = kk * 32 + tg * 4;
            uint32_t q_[4], kh_[8][2], kl_[8][2];
            {
                const char* p = smem + F4_Q + (wm + g) * 272 + cb;
                q_[0] = *(const uint32_t*)(p);
                q_[1] = *(const uint32_t*)(p + 8 * 272);
                q_[2] = *(const uint32_t*)(p + 16);
                q_[3] = *(const uint32_t*)(p + 8 * 272 + 16);
            }
            #pragma unroll
            for (int nt = 0; nt < 8; nt++) {
                const char* p = (const char*)smem + (kcur - sb) + (nt * 8 + g) * 272 + cb;
                kh_[nt][0] = *(const uint32_t*)(p);
                kh_[nt][1] = *(const uint32_t*)(p + 16);
                kl_[nt][0] = *(const uint32_t*)(p + F4_KLOF);
                kl_[nt][1] = *(const uint32_t*)(p + F4_KLOF + 16);
            }
            #pragma unroll
            for (int nt = 0; nt < 8; nt++) {
                mma_fp16(sacc[nt], q_, kh_[nt]);
                mma_fp16(sacc[nt], q_, kl_[nt]);
            }
        }

        uint32_t ph_[4][4];
        #pragma unroll
        for (int nt = 0; nt < 8; nt++) {
            const int col0 = nt * 8 + 2 * tg;
            const int gc   = it * 64 + col0;
            float b0 = -SHIFT, b1 = -SHIFT;
            if (gc >= Nq) { b0 = sYB[gc - Nq]; b1 = sYB[gc - Nq + 1]; }
            const float p0 = __expf(sacc[nt][0] * SCALE + b0);
            const float p1 = __expf(sacc[nt][1] * SCALE + b1);
            const float p2 = __expf(sacc[nt][2] * SCALE + b0);
            const float p3 = __expf(sacc[nt][3] * SCALE + b1);
            rowsum0 += p0 + p1;
            rowsum1 += p2 + p3;
            const int j  = nt >> 1;
            const int rb = (nt & 1) * 2;
            ph_[j][rb + 0] = pack_hf2(p0, p1);
            ph_[j][rb + 1] = pack_hf2(p2, p3);
        }

        CP_WAIT(1);
        __syncthreads();

        #pragma unroll
        for (int j = 0; j < 4; j++) {
            const int cb = j * 32 + tg * 4;
            #pragma unroll
            for (int nt = 0; nt < 16; nt++) {
                uint32_t vh_[2], vl_[2];
                const char* p = smem + F4_VH + (nt * 8 + g) * 144 + cb;
                vh_[0] = *(const uint32_t*)(p);
                vh_[1] = *(const uint32_t*)(p + 16);
                vl_[0] = *(const uint32_t*)(p + (F4_VL - F4_VH));
                vl_[1] = *(const uint32_t*)(p + (F4_VL - F4_VH) + 16);
                mma_fp16(oacc[nt], ph_[j], vh_);
                mma_fp16(oacc[nt], ph_[j], vl_);
            }
        }
    }

    rowsum0 += __shfl_xor_sync(0xffffffffu, rowsum0, 1);
    rowsum0 += __shfl_xor_sync(0xffffffffu, rowsum0, 2);
    rowsum1 += __shfl_xor_sync(0xffffffffu, rowsum1, 1);
    rowsum1 += __shfl_xor_sync(0xffffffffu, rowsum1, 2);
    const float inv0 = 1.f / rowsum0;
    const float inv1 = 1.f / rowsum1;

    const int r = wm + g;
    #pragma unroll
    for (int nt = 0; nt < 16; nt++) {
        const int col = nt * 8 + 2 * tg;
        const long long o0 = ((long long)b * Nq + q0 + r) * Cdim + h * HDim + col;
        const long long o1 = o0 + 8LL * Cdim;
        __half2 v0, v1;
        v0.x = __float2half(oacc[nt][0] * inv0);
        v0.y = __float2half(oacc[nt][1] * inv0);
        v1.x = __float2half(oacc[nt][2] * inv1);
        v1.y = __float2half(oacc[nt][3] * inv1);
        *(__half2*)(Oh + o0) = v0;
        *(__half2*)(Oh + o1) = v1;
    }
}

// ---------------- fp32 -> single fp16, two tensors in one launch ----------------
__global__ void cvt_single2(const float* __restrict__ s1, __half* __restrict__ h1, long long n1,
                            const float* __restrict__ s2, __half* __restrict__ h2, long long n2)
{
    long long i = ((long long)blockIdx.x * blockDim.x + threadIdx.x) * 4;
    const float* src; __half* h;
    if (i < n1) { src = s1; h = h1; }
    else        { i -= n1; if (i >= n2) return; src = s2; h = h2; }
    const float4 v = *(const float4*)(src + i);
    __half hb[4];
    hb[0] = __float2half(v.x); hb[1] = __float2half(v.y);
    hb[2] = __float2half(v.z); hb[3] = __float2half(v.w);
    *(uint2*)(h + i) = *(uint2*)hb;
}

// ---------------- fp32 [K][N] -> single fp16 transposed [N][K]; 3 weights packed ----
constexpr int WQ_BLKS = (3 * Cdim / 32) * (Cdim / 32);   // 6912
constexpr int WK_BLKS = (2 * Cdim / 32) * (Cdim / 32);   // 4608
constexpr int WP_BLKS = (Cdim / 32) * (Cdim / 32);       // 2304

__global__ void cvt_single_T3(const float* __restrict__ W1, __half* __restrict__ h1,
                              const float* __restrict__ W2, __half* __restrict__ h2,
                              const float* __restrict__ W3, __half* __restrict__ h3)
{
    __shared__ float tile[32][33];
    const int tid = threadIdx.x;
    const int tx = tid & 31;
    const int ty = tid >> 5;

    const float* W; __half* h;
    int N, n0, k0;
    int bid = blockIdx.x;
    if (bid < WQ_BLKS) {
        W = W1; h = h1; N = 3 * Cdim;
    } else if (bid < WQ_BLKS + WK_BLKS) {
        bid -= WQ_BLKS;
        W = W2; h = h2; N = 2 * Cdim;
    } else {
        bid -= WQ_BLKS + WK_BLKS;
        W = W3; h = h3; N = Cdim;
    }
    n0 = (bid % (N / 32)) * 32;  k0 = (bid / (N / 32)) * 32;

    #pragma unroll
    for (int i = ty; i < 32; i += 8)
        tile[i][tx] = W[(long long)(k0 + i) * N + n0 + tx];
    __syncthreads();
    #pragma unroll
    for (int i = ty; i < 32; i += 8) {
        const long long o = (long long)(n0 + i) * Cdim + k0 + tx;
        h[o] = __float2half(tile[tx][i]);
    }
}

// ---------------- V: fp32 [bh][s][d] -> split fp16 transposed [bh][d][s] ----------
__global__ void v_transpose_split(const float* __restrict__ Vb,
                                  __half* __restrict__ Vth,
                                  __half* __restrict__ Vtl)
{
    __shared__ float tile[32][33];
    const int z  = blockIdx.z;
    const int ss0 = blockIdx.x * 32;
    const int dd0 = blockIdx.y * 32;
    const int tx = threadIdx.x;
    const int ty = threadIdx.y;
    const long long ib = (long long)z * Sk * HDim;
    const long long ob = (long long)z * HDim * Sk;
    #pragma unroll
    for (int i = ty; i < 32; i += 8)
        tile[i][tx] = Vb[ib + (long long)(ss0 + i) * HDim + dd0 + tx];
    __syncthreads();
    #pragma unroll
    for (int i = ty; i < 32; i += 8) {
        const float v = tile[tx][i];
        const __half hb = __float2half(v);
        const __half lb = __float2half(v - __half2float(hb));
        const long long o = ob + (long long)(dd0 + i) * Sk + ss0 + tx;
        Vth[o] = hb; Vtl[o] = lb;
    }
}

// ---------------- warp reduction helpers ----------------
__device__ __forceinline__ float warpSum(float v) {
    #pragma unroll
    for (int o = 16; o > 0; o >>= 1) v += __shfl_xor_sync(0xffffffffu, v, o);
    return v;
}

// ---------------- QKV postprocess: RMSNorm + RoPE -> fp16 Q(single), K(split); fp32 V
__global__ void qkv_post(const float* __restrict__ qkv, const float* __restrict__ pos,
                         const float* __restrict__ qw, const float* __restrict__ kw,
                         __half* __restrict__ Qs,
                         __half* __restrict__ Kh, __half* __restrict__ Kl,
                         float* __restrict__ Vb)
{
    const int idx = blockIdx.x;
    const int h  = idx % Hn;
    const int bn = idx / Hn;
    const int n  = bn % Nq;
    const int b  = bn / Nq;
    const int d  = threadIdx.x;

    const float* row = qkv + (long long)bn * (3 * Cdim);
    const float qv = row[h * HDim + d];
    const float kv = row[Cdim + h * HDim + d];
    const float vv = row[2 * Cdim + h * HDim + d];

    __shared__ float sred[8];
    __shared__ float qs[HDim], ks[HDim];

    const float sq = warpSum(qv * qv);
    const float sk = warpSum(kv * kv);
    const int lane = d & 31, w = d >> 5;
    if (lane == 0) { sred[w] = sq; sred[4 + w] = sk; }
    __syncthreads();
    const float sumq = sred[0] + sred[1] + sred[2] + sred[3];
    const float sumk = sred[4] + sred[5] + sred[6] + sred[7];
    const float rq = rsqrtf(sumq * (1.0f / HDim) + EPSV);
    const float rk = rsqrtf(sumk * (1.0f / HDim) + EPSV);
    const float qn = qw[d] * qv * rq;
    const float kn = kw[d] * kv * rk;
    qs[d] = qn; ks[d] = kn;
    __syncthreads();

    float qo = qn, ko = kn;
    if (d < RD) {
        const int j = d & 31;
        const float c = pos[(n * 32 + j) * 2 + 0];
        const float s = pos[(n * 32 + j) * 2 + 1];
        if (d < RD / 2) { qo = qs[d] * c - qs[d + 32] * s;  ko = ks[d] * c - ks[d + 32] * s; }
        else            { qo = qs[d - 32] * s + qs[d] * c;  ko = ks[d - 32] * s + ks[d] * c; }
    }
    const long long qi = (((long long)(b * Hn + h)) * Nq + n) * HDim + d;
    const long long ki = (((long long)(b * Hn + h)) * Sk + n) * HDim + d;
    Qs[qi] = __float2half(qo);
    split_write_h(ko, Kh, Kl, ki);
    Vb[ki] = vv;
}

// ---------------- KV(y) postprocess ----------------
__global__ void kv_post(const float* __restrict__ kvr, const float* __restrict__ kw,
                        __half* __restrict__ Kh, __half* __restrict__ Kl,
                        float* __restrict__ Vb)
{
    const int idx = blockIdx.x;
    const int h  = idx % Hn;
    const int bm = idx / Hn;
    const int m  = bm % My;
    const int b  = bm / My;
    const int d  = threadIdx.x;

    const float* row = kvr + (long long)bm * (2 * Cdim);
    const float kv = row[h * HDim + d];
    const float vv = row[Cdim + h * HDim + d];

    __shared__ float sred[4];
    const float sk = warpSum(kv * kv);
    if ((d & 31) == 0) sred[d >> 5] = sk;
    __syncthreads();
    const float sumk = sred[0] + sred[1] + sred[2] + sred[3];
    const float rk = rsqrtf(sumk * (1.0f / HDim) + EPSV);
    const float kn = kw[d] * kv * rk;

    const long long ki = (((long long)(b * Hn + h)) * Sk + (Nq + m)) * HDim + d;
    split_write_h(kn, Kh, Kl, ki);
    Vb[ki] = vv;
}

// ---------------- launch ----------------
extern "C" void kernel_launch(void* const* d_in, const int* in_sizes, int n_in,
                              void* d_out, int out_size)
{
    const float* x    = (const float*)d_in[0];
    const float* y    = (const float*)d_in[1];
    const float* pos  = (const float*)d_in[2];
    const float* ytw  = (const float*)d_in[3];
    const float* Wqkv = (const float*)d_in[4];
    const float* Wkv  = (const float*)d_in[5];
    const float* qw   = (const float*)d_in[6];
    const float* kw   = (const float*)d_in[7];
    const float* Wproj= (const float*)d_in[8];
    const float* bproj= (const float*)d_in[9];
    float* out = (float*)d_out;

    float *qkv, *kvr, *Vb;
    cudaGetSymbolAddress((void**)&qkv, g_qkv);
    cudaGetSymbolAddress((void**)&kvr, g_kvr);
    cudaGetSymbolAddress((void**)&Vb,  g_Vb);

    __half *xh,*yh,*Wq,*Wk,*Wp,*Oh;
    __half *Qs,*Kh,*Kl,*Vth,*Vtl;
    cudaGetSymbolAddress((void**)&xh, g_xh);
    cudaGetSymbolAddress((void**)&yh, g_yh);
    cudaGetSymbolAddress((void**)&Wq, g_Wqkvh);
    cudaGetSymbolAddress((void**)&Wk, g_Wkvh);
    cudaGetSymbolAddress((void**)&Wp, g_Wph);
    cudaGetSymbolAddress((void**)&Oh, g_Oh);
    cudaGetSymbolAddress((void**)&Qs, g_Qs);
    cudaGetSymbolAddress((void**)&Kh, g_Kh);     cudaGetSymbolAddress((void**)&Kl, g_Kl);
    cudaGetSymbolAddress((void**)&Vth, g_Vth);   cudaGetSymbolAddress((void**)&Vtl, g_Vtl);

    cudaFuncSetAttribute(mma_gemm_fused, cudaFuncAttributeMaxDynamicSharedMemorySize, MM_SMEM_B);
    cudaFuncSetAttribute(mma_gemm_proj,  cudaFuncAttributeMaxDynamicSharedMemorySize, MM_SMEM_B);
    cudaFuncSetAttribute(fused_attn, cudaFuncAttributeMaxDynamicSharedMemorySize, FA_SMEM);

    // 0) conversions: activations + all 3 weights to single fp16 (transposed)
    const long long nx = (long long)Bsz * Nq * Cdim;
    const long long ny = (long long)Bsz * My * Cdim;
    cvt_single2<<<(int)(((nx + ny) / 4 + 255) / 256), 256>>>(x, xh, nx, y, yh, ny);
    cvt_single_T3<<<WQ_BLKS + WK_BLKS + WP_BLKS, 256>>>(Wqkv, Wq, Wkv, Wk, Wproj, Wp);

    // 1+2) fused QKV + KV weight GEMM (plain fp16, 1 product)
    mma_gemm_fused<<<FUSED_CTAS, 256, MM_SMEM_B>>>(
        xh, Wq, qkv, yh, Wk, kvr);

    // 3) postprocess (fp16 attention operands)
    qkv_post<<<Bsz * Nq * Hn, HDim>>>(qkv, pos, qw, kw, Qs, Kh, Kl, Vb);
    kv_post<<<Bsz * My * Hn, HDim>>>(kvr, kw, Kh, Kl, Vb);
    v_transpose_split<<<dim3(Sk / 32, HDim / 32, Bsz * Hn), dim3(32, 8)>>>(Vb, Vth, Vtl);

    // 4-6) fused attention v4 (fp16) -> single fp16 O
    fused_attn<<<dim3(Nq / 128, Bsz * Hn), 256, FA_SMEM>>>(
        Qs, Kh, Kl, Vth, Vtl, ytw, Oh);

    // 7) out = O @ Wproj + bproj (plain fp16, 1 product)
    mma_gemm_proj<<<dim3(Cdim / 128, Bsz * Nq / 128), 256, MM_SMEM_B>>>(
        Oh, Wp, out, bproj);
}